// round 6
// baseline (speedup 1.0000x reference)
#include <cuda_runtime.h>
#include <cuda_bf16.h>
#include <math.h>
#include <stdint.h>

static constexpr int kS = 2048;
static constexpr int kD = 2048;
static constexpr int kH = 32;
static constexpr int kN = 64;
static constexpr size_t kSD = (size_t)kS * kD;
static constexpr int kKSPLIT = 16;

// ---------------- scratch (device globals; no allocation allowed) ----------------
__device__ float g_xn[kSD];
__device__ float g_xr[kSD];
__device__ float g_xw[kSD];
__device__ float g_xk[kSD];
__device__ float g_xv[kSD];
__device__ float g_xa[kSD];
__device__ float g_xg[kSD];
__device__ float g_r[kSD];
__device__ float g_k[kSD];
__device__ float g_v[kSD];
__device__ float g_a[kSD];
__device__ float g_wdec[kSD];
__device__ float g_gate[kSD];
__device__ float g_kk[kSD];
__device__ float g_b[kSD];
__device__ float g_y[kSD];
__device__ float g_opre[kSD];
__device__ float g_tmpD[kSD];
__device__ float g_t1[(size_t)kS * 128];
__device__ float g_part[(size_t)kKSPLIT * kS * 128];
// bf16 split buffers for tensor-core GEMMs
__device__ __nv_bfloat16 g_ah[kSD];
__device__ __nv_bfloat16 g_al[kSD];
__device__ __nv_bfloat16 g_wh[kSD];
__device__ __nv_bfloat16 g_wl[kSD];

__device__ __forceinline__ float warp_sum(float v) {
    #pragma unroll
    for (int o = 16; o > 0; o >>= 1) v += __shfl_xor_sync(0xffffffffu, v, o);
    return v;
}

__device__ __forceinline__ float sigmoidf_(float x) { return 1.f / (1.f + expf(-x)); }

// packed f32x2 helpers (FFMA2 — ptxas only emits via explicit PTX)
__device__ __forceinline__ float2 ffma2(float2 a, float2 b, float2 c) {
    float2 d;
    asm("fma.rn.f32x2 %0, %1, %2, %3;"
        : "=l"(reinterpret_cast<unsigned long long&>(d))
        : "l"(reinterpret_cast<unsigned long long&>(a)),
          "l"(reinterpret_cast<unsigned long long&>(b)),
          "l"(reinterpret_cast<unsigned long long&>(c)));
    return d;
}
__device__ __forceinline__ float2 fmul2(float2 a, float2 b) {
    float2 d;
    asm("mul.rn.f32x2 %0, %1, %2;"
        : "=l"(reinterpret_cast<unsigned long long&>(d))
        : "l"(reinterpret_cast<unsigned long long&>(a)),
          "l"(reinterpret_cast<unsigned long long&>(b)));
    return d;
}

// ---------------- mma / ldmatrix / cp.async primitives ----------------
__device__ __forceinline__ uint32_t smem_u32(const void* p) {
    return (uint32_t)__cvta_generic_to_shared(p);
}
__device__ __forceinline__ void cp16(uint32_t dst, const void* src) {
    asm volatile("cp.async.cg.shared.global [%0], [%1], 16;" :: "r"(dst), "l"(src));
}
__device__ __forceinline__ void cp_commit() {
    asm volatile("cp.async.commit_group;" ::: "memory");
}
template<int N>
__device__ __forceinline__ void cp_wait() {
    asm volatile("cp.async.wait_group %0;" :: "n"(N) : "memory");
}
__device__ __forceinline__ void ldsm_x4(uint32_t* r, uint32_t addr) {
    asm volatile("ldmatrix.sync.aligned.m8n8.x4.shared.b16 {%0,%1,%2,%3}, [%4];"
                 : "=r"(r[0]), "=r"(r[1]), "=r"(r[2]), "=r"(r[3]) : "r"(addr));
}
__device__ __forceinline__ void mma_bf16(float* c, const uint32_t* a, uint32_t b0, uint32_t b1) {
    asm volatile("mma.sync.aligned.m16n8k16.row.col.f32.bf16.bf16.f32 "
                 "{%0,%1,%2,%3}, {%4,%5,%6,%7}, {%8,%9}, {%0,%1,%2,%3};"
                 : "+f"(c[0]), "+f"(c[1]), "+f"(c[2]), "+f"(c[3])
                 : "r"(a[0]), "r"(a[1]), "r"(a[2]), "r"(a[3]), "r"(b0), "r"(b1));
}

// ---------------- fp32 -> (hi, lo) bf16 split ----------------
__global__ void split_bf16_kernel(const float4* __restrict__ src,
                                  __nv_bfloat162* __restrict__ hi,
                                  __nv_bfloat162* __restrict__ lo, int n4)
{
    int i = blockIdx.x * blockDim.x + threadIdx.x;
    if (i >= n4) return;
    float4 v = src[i];
    __nv_bfloat16 h0 = __float2bfloat16_rn(v.x);
    __nv_bfloat16 h1 = __float2bfloat16_rn(v.y);
    __nv_bfloat16 h2 = __float2bfloat16_rn(v.z);
    __nv_bfloat16 h3 = __float2bfloat16_rn(v.w);
    __nv_bfloat16 l0 = __float2bfloat16_rn(v.x - __bfloat162float(h0));
    __nv_bfloat16 l1 = __float2bfloat16_rn(v.y - __bfloat162float(h1));
    __nv_bfloat16 l2 = __float2bfloat16_rn(v.z - __bfloat162float(h2));
    __nv_bfloat16 l3 = __float2bfloat16_rn(v.w - __bfloat162float(h3));
    hi[2 * i + 0] = __nv_bfloat162(h0, h1);
    hi[2 * i + 1] = __nv_bfloat162(h2, h3);
    lo[2 * i + 0] = __nv_bfloat162(l0, l1);
    lo[2 * i + 1] = __nv_bfloat162(l2, l3);
}

// ---------------- bf16x3 tensor-core NT GEMM: C = Ah@Bh^T + Ah@Bl^T + Al@Bh^T ----
// fixed M=N=K=2048. Block 128x128, BK=32, 8 warps (warp tile 64x32), cp.async 2-stage.
static constexpr int kLDB  = 80;      // bytes per smem row (32 bf16 + 8 pad)
static constexpr int kARR  = 128 * kLDB;   // 10240 B per array
static constexpr int kSTG  = 4 * kARR;     // 40960 B per stage
static constexpr int kSMEM = 2 * kSTG;     // 81920 B total

__global__ void __launch_bounds__(256, 1)
bf16x3_nt_kernel(const __nv_bfloat16* __restrict__ Ah, const __nv_bfloat16* __restrict__ Al,
                 const __nv_bfloat16* __restrict__ Bh, const __nv_bfloat16* __restrict__ Bl,
                 float* __restrict__ C, const float* __restrict__ resid)
{
    constexpr int Kk = 2048;
    constexpr int NT = Kk / 32;
    extern __shared__ char sm_raw[];
    uint32_t sbase = smem_u32(sm_raw);

    int tid = threadIdx.x, lane = tid & 31, wid = tid >> 5;
    int m0 = blockIdx.y * 128, n0 = blockIdx.x * 128;
    int wm = (wid >> 2) * 64;   // 0 / 64
    int wn = (wid & 3) * 32;    // 0/32/64/96

    float acc[4][4][4];
    #pragma unroll
    for (int mt = 0; mt < 4; mt++)
        #pragma unroll
        for (int nt = 0; nt < 4; nt++)
            #pragma unroll
            for (int q = 0; q < 4; q++) acc[mt][nt][q] = 0.f;

    // cp.async per-thread mapping: seg = 16B chunk within row (4 per row),
    // rows r0 and r0+64 of each of the 4 arrays (Ah, Al, Bh, Bl)
    int seg = tid & 3;
    int r0 = tid >> 2;   // 0..63
    const char* sAh0 = (const char*)(Ah + (size_t)(m0 + r0) * Kk + seg * 8);
    const char* sAl0 = (const char*)(Al + (size_t)(m0 + r0) * Kk + seg * 8);
    const char* sBh0 = (const char*)(Bh + (size_t)(n0 + r0) * Kk + seg * 8);
    const char* sBl0 = (const char*)(Bl + (size_t)(n0 + r0) * Kk + seg * 8);
    const size_t rstep = (size_t)64 * Kk * 2;   // +64 rows in bytes
    uint32_t d0 = (uint32_t)(r0 * kLDB + seg * 16);
    uint32_t d1 = (uint32_t)((r0 + 64) * kLDB + seg * 16);

    auto issue = [&](int kt) {
        uint32_t sb = sbase + (uint32_t)(kt & 1) * kSTG;
        size_t koff = (size_t)kt * 64;   // 32 bf16 = 64 bytes
        cp16(sb + 0 * kARR + d0, sAh0 + koff);
        cp16(sb + 0 * kARR + d1, sAh0 + rstep + koff);
        cp16(sb + 1 * kARR + d0, sAl0 + koff);
        cp16(sb + 1 * kARR + d1, sAl0 + rstep + koff);
        cp16(sb + 2 * kARR + d0, sBh0 + koff);
        cp16(sb + 2 * kARR + d1, sBh0 + rstep + koff);
        cp16(sb + 3 * kARR + d0, sBl0 + koff);
        cp16(sb + 3 * kARR + d1, sBl0 + rstep + koff);
        cp_commit();
    };

    issue(0);

    int frow = lane & 15;
    uint32_t fcol = (uint32_t)((lane >> 4) * 16);   // byte offset of k-half

    for (int kt = 0; kt < NT; ++kt) {
        if (kt + 1 < NT) { issue(kt + 1); cp_wait<1>(); }
        else             { cp_wait<0>(); }
        __syncthreads();

        uint32_t sb = sbase + (uint32_t)(kt & 1) * kSTG;
        #pragma unroll
        for (int kh = 0; kh < 2; kh++) {
            uint32_t kb = fcol + (uint32_t)(kh * 32);   // + k16 half in bytes
            uint32_t ah[4][4], al[4][4], bh[2][4], bl[2][4];
            #pragma unroll
            for (int mt = 0; mt < 4; mt++) {
                uint32_t ro = (uint32_t)((wm + mt * 16 + frow) * kLDB) + kb;
                ldsm_x4(ah[mt], sb + 0 * kARR + ro);
                ldsm_x4(al[mt], sb + 1 * kARR + ro);
            }
            #pragma unroll
            for (int g = 0; g < 2; g++) {
                uint32_t ro = (uint32_t)((wn + g * 16 + frow) * kLDB) + kb;
                ldsm_x4(bh[g], sb + 2 * kARR + ro);
                ldsm_x4(bl[g], sb + 3 * kARR + ro);
            }
            #pragma unroll
            for (int mt = 0; mt < 4; mt++) {
                #pragma unroll
                for (int nt = 0; nt < 4; nt++) {
                    int g = nt >> 1, hf = nt & 1;
                    mma_bf16(acc[mt][nt], ah[mt], bh[g][hf], bh[g][2 + hf]);
                    mma_bf16(acc[mt][nt], ah[mt], bl[g][hf], bl[g][2 + hf]);
                    mma_bf16(acc[mt][nt], al[mt], bh[g][hf], bh[g][2 + hf]);
                }
            }
        }
        __syncthreads();
    }

    // epilogue
    int crow = lane >> 2;
    int ccol = (lane & 3) * 2;
    #pragma unroll
    for (int mt = 0; mt < 4; mt++) {
        #pragma unroll
        for (int nt = 0; nt < 4; nt++) {
            int row = m0 + wm + mt * 16 + crow;
            int col = n0 + wn + nt * 8 + ccol;
            size_t o0 = (size_t)row * 2048 + col;
            size_t o1 = (size_t)(row + 8) * 2048 + col;
            float2 v0 = make_float2(acc[mt][nt][0], acc[mt][nt][1]);
            float2 v1 = make_float2(acc[mt][nt][2], acc[mt][nt][3]);
            if (resid) {
                const float2 r0v = *(const float2*)(resid + o0);
                const float2 r1v = *(const float2*)(resid + o1);
                v0.x += r0v.x; v0.y += r0v.y;
                v1.x += r1v.x; v1.y += r1v.y;
            }
            *(float2*)(C + o0) = v0;
            *(float2*)(C + o1) = v1;
        }
    }
}

// ---------------- LayerNorm over D per token ----------------
__global__ void ln_kernel(const float* __restrict__ x, const float* __restrict__ w,
                          const float* __restrict__ b, float* __restrict__ xn,
                          float* __restrict__ s1out)
{
    int s = blockIdx.x;
    int tid = threadIdx.x;
    size_t base = (size_t)s * kD;
    float vals[8];
    float sum = 0.f, sq = 0.f;
    #pragma unroll
    for (int i = 0; i < 8; i++) {
        float v = x[base + tid + i * 256];
        vals[i] = v; sum += v; sq += v * v;
    }
    __shared__ float sh1[256], sh2[256];
    sh1[tid] = sum; sh2[tid] = sq;
    __syncthreads();
    for (int off = 128; off > 0; off >>= 1) {
        if (tid < off) { sh1[tid] += sh1[tid + off]; sh2[tid] += sh2[tid + off]; }
        __syncthreads();
    }
    float mean = sh1[0] * (1.f / kD);
    float var  = sh2[0] * (1.f / kD) - mean * mean;
    float rstd = rsqrtf(var + 1e-5f);
    #pragma unroll
    for (int i = 0; i < 8; i++) {
        int d = tid + i * 256;
        float o = (vals[i] - mean) * rstd * w[d] + b[d];
        xn[base + d] = o;
        if (s1out && s == kS - 1) s1out[d] = o;
    }
}

// ---------------- token shift + 6 mixes ----------------
__global__ void shift_mix_kernel(const float* __restrict__ xn, const float* __restrict__ st1,
    const float* __restrict__ mr, const float* __restrict__ mw, const float* __restrict__ mk,
    const float* __restrict__ mv, const float* __restrict__ ma, const float* __restrict__ mg)
{
    size_t idx = (size_t)blockIdx.x * blockDim.x + threadIdx.x;
    if (idx >= kSD) return;
    int d = (int)(idx & (size_t)(kD - 1));
    float cur = xn[idx];
    float past = (idx < (size_t)kD) ? st1[d] : xn[idx - kD];
    float sx = past - cur;
    g_xr[idx] = cur + sx * mr[d];
    g_xw[idx] = cur + sx * mw[d];
    g_xk[idx] = cur + sx * mk[d];
    g_xv[idx] = cur + sx * mv[d];
    g_xa[idx] = cur + sx * ma[d];
    g_xg[idx] = cur + sx * mg[d];
}

// ---------------- generic tiled SGEMM (kept for NN medium GEMMs) ----------------
template<int BM, int BN, int BK, int TM, int TN, bool BT>
__global__ void __launch_bounds__((BM/TM)*(BN/TN))
sgemm_kernel(const float* __restrict__ A, const float* __restrict__ B,
             float* __restrict__ C, int M, int Nn, int K,
             const float* __restrict__ resid)
{
    constexpr int THREADS = (BM / TM) * (BN / TN);
    __shared__ float As[BK][BM + 4];
    __shared__ float Bs[BK][BN + 4];
    int tid = threadIdx.x;
    int m0 = blockIdx.y * BM;
    int n0 = blockIdx.x * BN;
    int tx = tid % (BN / TN);
    int ty = tid / (BN / TN);
    float acc[TM][TN];
    #pragma unroll
    for (int i = 0; i < TM; i++)
        #pragma unroll
        for (int j = 0; j < TN; j++) acc[i][j] = 0.f;

    constexpr int KQ = BK / 4;
    constexpr int A_F4 = BM * BK / 4;
    constexpr int A_PER = A_F4 / THREADS;
    static_assert(A_F4 % THREADS == 0, "A load");
    constexpr int B_F4 = BN * BK / 4;
    constexpr int B_PER = B_F4 / THREADS;
    static_assert(B_F4 % THREADS == 0, "B load");

    for (int k0 = 0; k0 < K; k0 += BK) {
        #pragma unroll
        for (int i = 0; i < A_PER; i++) {
            int e = tid + i * THREADS;
            int row = e / KQ, kq = e % KQ;
            float4 v = *(const float4*)&A[(size_t)(m0 + row) * K + k0 + kq * 4];
            As[kq * 4 + 0][row] = v.x; As[kq * 4 + 1][row] = v.y;
            As[kq * 4 + 2][row] = v.z; As[kq * 4 + 3][row] = v.w;
        }
        if (BT) {
            #pragma unroll
            for (int i = 0; i < B_PER; i++) {
                int e = tid + i * THREADS;
                int row = e / KQ, kq = e % KQ;
                float4 v = *(const float4*)&B[(size_t)(n0 + row) * K + k0 + kq * 4];
                Bs[kq * 4 + 0][row] = v.x; Bs[kq * 4 + 1][row] = v.y;
                Bs[kq * 4 + 2][row] = v.z; Bs[kq * 4 + 3][row] = v.w;
            }
        } else {
            constexpr int NQ = BN / 4;
            #pragma unroll
            for (int i = 0; i < B_PER; i++) {
                int e = tid + i * THREADS;
                int row = e / NQ, nq = e % NQ;
                float4 v = *(const float4*)&B[(size_t)(k0 + row) * Nn + n0 + nq * 4];
                *(float4*)&Bs[row][nq * 4] = v;
            }
        }
        __syncthreads();
        #pragma unroll
        for (int k = 0; k < BK; k++) {
            float af[TM], bf[TN];
            #pragma unroll
            for (int i = 0; i < TM; i++) af[i] = As[k][ty * TM + i];
            #pragma unroll
            for (int j = 0; j < TN; j++) bf[j] = Bs[k][tx * TN + j];
            #pragma unroll
            for (int i = 0; i < TM; i++)
                #pragma unroll
                for (int j = 0; j < TN; j++)
                    acc[i][j] += af[i] * bf[j];
        }
        __syncthreads();
    }
    #pragma unroll
    for (int i = 0; i < TM; i++) {
        size_t rowoff = (size_t)(m0 + ty * TM + i) * Nn + n0 + tx * TN;
        #pragma unroll
        for (int j = 0; j < TN; j++) {
            float v = acc[i][j];
            if (resid) v += resid[rowoff + j];
            C[rowoff + j] = v;
        }
    }
}

// ---------------- split-K thin GEMM (NN): part[ks][M][N] partials ----------------
template<int BM, int BN, int BK, int TM, int TN>
__global__ void __launch_bounds__((BM/TM)*(BN/TN))
gemm_splitk_kernel(const float* __restrict__ A, const float* __restrict__ B,
                   float* __restrict__ part, int M, int Nn, int K)
{
    constexpr int THREADS = (BM / TM) * (BN / TN);
    __shared__ float As[BK][BM + 4];
    __shared__ float Bs[BK][BN + 4];
    int tid = threadIdx.x;
    int m0 = blockIdx.y * BM;
    int ks = blockIdx.z;
    int kc = K / kKSPLIT;
    int kbeg = ks * kc;
    int tx = tid % (BN / TN);
    int ty = tid / (BN / TN);
    float acc[TM][TN];
    #pragma unroll
    for (int i = 0; i < TM; i++)
        #pragma unroll
        for (int j = 0; j < TN; j++) acc[i][j] = 0.f;

    constexpr int KQ = BK / 4;
    constexpr int A_F4 = BM * BK / 4;
    constexpr int A_PER = A_F4 / THREADS;
    static_assert(A_F4 % THREADS == 0, "A load");
    constexpr int B_F4 = BN * BK / 4;
    constexpr int B_PER = B_F4 / THREADS;
    static_assert(B_F4 % THREADS == 0, "B load");
    constexpr int NQ = BN / 4;

    for (int k0 = kbeg; k0 < kbeg + kc; k0 += BK) {
        #pragma unroll
        for (int i = 0; i < A_PER; i++) {
            int e = tid + i * THREADS;
            int row = e / KQ, kq = e % KQ;
            float4 v = *(const float4*)&A[(size_t)(m0 + row) * K + k0 + kq * 4];
            As[kq * 4 + 0][row] = v.x; As[kq * 4 + 1][row] = v.y;
            As[kq * 4 + 2][row] = v.z; As[kq * 4 + 3][row] = v.w;
        }
        #pragma unroll
        for (int i = 0; i < B_PER; i++) {
            int e = tid + i * THREADS;
            int row = e / NQ, nq = e % NQ;
            float4 v = *(const float4*)&B[(size_t)(k0 + row) * Nn + nq * 4];
            *(float4*)&Bs[row][nq * 4] = v;
        }
        __syncthreads();
        #pragma unroll
        for (int k = 0; k < BK; k++) {
            float af[TM], bf[TN];
            #pragma unroll
            for (int i = 0; i < TM; i++) af[i] = As[k][ty * TM + i];
            #pragma unroll
            for (int j = 0; j < TN; j++) bf[j] = Bs[k][tx * TN + j];
            #pragma unroll
            for (int i = 0; i < TM; i++)
                #pragma unroll
                for (int j = 0; j < TN; j++)
                    acc[i][j] += af[i] * bf[j];
        }
        __syncthreads();
    }
    float* pbase = part + (size_t)ks * M * Nn;
    #pragma unroll
    for (int i = 0; i < TM; i++) {
        size_t rowoff = (size_t)(m0 + ty * TM + i) * Nn + tx * TN;
        #pragma unroll
        for (int j = 0; j < TN; j++) pbase[rowoff + j] = acc[i][j];
    }
}

// act: 0 none, 1 sigmoid, 2 tanh
__global__ void splitk_reduce_kernel(const float* __restrict__ part, float* __restrict__ out,
                                     int MN, int act)
{
    int i = blockIdx.x * blockDim.x + threadIdx.x;
    if (i >= MN) return;
    float s = 0.f;
    #pragma unroll
    for (int ks = 0; ks < kKSPLIT; ks++) s += part[(size_t)ks * MN + i];
    if (act == 1) s = sigmoidf_(s);
    else if (act == 2) s = tanhf(s);
    out[i] = s;
}

// ---------------- elementwise epilogues ----------------
__global__ void a_epi_kernel(const float* __restrict__ t, const float* __restrict__ a0,
                             float* __restrict__ out) {
    size_t idx = (size_t)blockIdx.x * blockDim.x + threadIdx.x;
    if (idx >= kSD) return;
    int d = (int)(idx & (size_t)(kD - 1));
    out[idx] = sigmoidf_(t[idx] + a0[d]);
}
__global__ void w_epi_kernel(const float* __restrict__ t, const float* __restrict__ w0,
                             float* __restrict__ out) {
    size_t idx = (size_t)blockIdx.x * blockDim.x + threadIdx.x;
    if (idx >= kSD) return;
    int d = (int)(idx & (size_t)(kD - 1));
    float sg = sigmoidf_(t[idx] + w0[d]);
    out[idx] = expf(-0.606531f * sg);
}
__global__ void v_epi_kernel(const float* __restrict__ t, const float* __restrict__ v0,
                             const float* __restrict__ vfirst, float* __restrict__ vio) {
    size_t idx = (size_t)blockIdx.x * blockDim.x + threadIdx.x;
    if (idx >= kSD) return;
    int d = (int)(idx & (size_t)(kD - 1));
    float sg = sigmoidf_(t[idx] + v0[d]);
    float vr = vio[idx];
    vio[idx] = vr + (vfirst[idx] - vr) * sg;
}

// ---------------- per-(s,h) prep: kk normalize, b, k-mod ----------------
__global__ void prep_kernel(const float* __restrict__ k_in, const float* __restrict__ a,
                            const float* __restrict__ k_k, const float* __restrict__ k_a,
                            float* __restrict__ kk_out, float* __restrict__ b_out,
                            float* __restrict__ k_out)
{
    int gwarp = (int)((blockIdx.x * (size_t)blockDim.x + threadIdx.x) >> 5);
    int lane = threadIdx.x & 31;
    if (gwarp >= kS * kH) return;
    int s = gwarp >> 5, h = gwarp & (kH - 1);
    size_t base = (size_t)s * kD + (size_t)h * kN;
    int d0 = h * kN + lane, d1 = d0 + 32;
    float k0 = k_in[base + lane], k1 = k_in[base + lane + 32];
    float kk0 = k0 * k_k[d0], kk1 = k1 * k_k[d1];
    float ss = warp_sum(kk0 * kk0 + kk1 * kk1);
    float inv = 1.f / fmaxf(sqrtf(ss), 1e-12f);
    kk0 *= inv; kk1 *= inv;
    float a0 = a[base + lane], a1 = a[base + lane + 32];
    kk_out[base + lane] = kk0;        kk_out[base + lane + 32] = kk1;
    b_out[base + lane]  = kk0 * a0;   b_out[base + lane + 32]  = kk1 * a1;
    k_out[base + lane]      = k0 * (1.f + (a0 - 1.f) * k_a[d0]);
    k_out[base + lane + 32] = k1 * (1.f + (a1 - 1.f) * k_a[d1]);
}

// ---------------- sequential RWKV7 state scan v2 ----------------
__global__ void __launch_bounds__(256, 1)
scan2_kernel(const float* __restrict__ r, const float* __restrict__ w,
             const float* __restrict__ k, const float* __restrict__ v,
             const float* __restrict__ kk, const float* __restrict__ b,
             const float* __restrict__ st2_in, float* __restrict__ y,
             float* __restrict__ st2_out)
{
    int h = blockIdx.x;
    int tid = threadIdx.x;
    int jq = tid & 3;
    int i = tid >> 2;

    float2 st[8];
    const float2* sin = (const float2*)(st2_in + (size_t)h * kN * kN + (size_t)i * kN + jq * 16);
    #pragma unroll
    for (int m = 0; m < 8; m++) st[m] = sin[m];

    __shared__ __align__(16) float sbuf[2][6][kN];  // order: r, w, k, b, -kk, v

    int arr = tid >> 4;
    int idx = tid & 15;
    const float* src = nullptr;
    if (tid < 96) {
        if (arr == 0) src = r;
        else if (arr == 1) src = w;
        else if (arr == 2) src = k;
        else if (arr == 3) src = b;
        else if (arr == 4) src = kk;
        else src = v;
    }
    size_t gbase = (size_t)h * kN + idx * 4;
    float4 pf = make_float4(0.f, 0.f, 0.f, 0.f);
    if (tid < 96) pf = *(const float4*)(src + gbase);

    for (int t = 0; t < kS; t++) {
        int buf = t & 1;
        if (tid < 96) {
            float4 vv = pf;
            if (arr == 4) { vv.x = -vv.x; vv.y = -vv.y; vv.z = -vv.z; vv.w = -vv.w; }
            *(float4*)&sbuf[buf][arr][idx * 4] = vv;
        }
        __syncthreads();
        if (t + 1 < kS && tid < 96)
            pf = *(const float4*)(src + (size_t)(t + 1) * kD + gbase);

        const float2* r2  = (const float2*)&sbuf[buf][0][jq * 16];
        const float2* w2  = (const float2*)&sbuf[buf][1][jq * 16];
        const float2* k2  = (const float2*)&sbuf[buf][2][jq * 16];
        const float2* b2  = (const float2*)&sbuf[buf][3][jq * 16];
        const float2* na2 = (const float2*)&sbuf[buf][4][jq * 16];

        float2 acc = make_float2(0.f, 0.f);
        #pragma unroll
        for (int m = 0; m < 8; m++) acc = ffma2(st[m], na2[m], acc);
        float sa = acc.x + acc.y;
        sa += __shfl_xor_sync(0xffffffffu, sa, 1);
        sa += __shfl_xor_sync(0xffffffffu, sa, 2);

        float vi = sbuf[buf][5][i];
        float2 sav = make_float2(sa, sa);
        float2 viv = make_float2(vi, vi);
        float2 yacc = make_float2(0.f, 0.f);
        #pragma unroll
        for (int m = 0; m < 8; m++) {
            float2 tmp = fmul2(viv, k2[m]);
            tmp = ffma2(sav, b2[m], tmp);
            float2 s2 = ffma2(st[m], w2[m], tmp);
            st[m] = s2;
            yacc = ffma2(s2, r2[m], yacc);
        }
        float yv = yacc.x + yacc.y;
        yv += __shfl_xor_sync(0xffffffffu, yv, 1);
        yv += __shfl_xor_sync(0xffffffffu, yv, 2);
        if (jq == 0) y[(size_t)t * kD + (size_t)h * kN + i] = yv;
    }
    if (st2_out) {
        float2* sout = (float2*)(st2_out + (size_t)h * kN * kN + (size_t)i * kN + jq * 16);
        #pragma unroll
        for (int m = 0; m < 8; m++) sout[m] = st[m];
    }
}

// ---------------- groupnorm + rkv + gate epilogue ----------------
__global__ void post_kernel(const float* __restrict__ y, const float* __restrict__ r,
                            const float* __restrict__ k, const float* __restrict__ v,
                            const float* __restrict__ r_k, const float* __restrict__ lnxw,
                            const float* __restrict__ lnxb, const float* __restrict__ gate,
                            float* __restrict__ opre)
{
    int gwarp = (int)((blockIdx.x * (size_t)blockDim.x + threadIdx.x) >> 5);
    int lane = threadIdx.x & 31;
    if (gwarp >= kS * kH) return;
    int s = gwarp >> 5, h = gwarp & (kH - 1);
    size_t base = (size_t)s * kD + (size_t)h * kN;
    int d0 = h * kN + lane, d1 = d0 + 32;
    float y0 = y[base + lane], y1 = y[base + lane + 32];
    float sum = warp_sum(y0 + y1);
    float sq  = warp_sum(y0 * y0 + y1 * y1);
    float mean = sum * (1.f / kN);
    float var  = sq * (1.f / kN) - mean * mean;
    float rstd = rsqrtf(var + 0.00064f);
    float o0 = (y0 - mean) * rstd * lnxw[d0] + lnxb[d0];
    float o1 = (y1 - mean) * rstd * lnxw[d1] + lnxb[d1];
    float r0 = r[base + lane], r1 = r[base + lane + 32];
    float k0 = k[base + lane], k1 = k[base + lane + 32];
    float dot = warp_sum(r0 * k0 * r_k[d0] + r1 * k1 * r_k[d1]);
    float v0 = v[base + lane], v1 = v[base + lane + 32];
    opre[base + lane]      = (o0 + dot * v0) * gate[base + lane];
    opre[base + lane + 32] = (o1 + dot * v1) * gate[base + lane + 32];
}

// ---------------- host side ----------------
static float* getsym(const void* symbol) {
    void* p = nullptr;
    cudaGetSymbolAddress(&p, symbol);
    return (float*)p;
}
static __nv_bfloat16* getsym_bf(const void* symbol) {
    void* p = nullptr;
    cudaGetSymbolAddress(&p, symbol);
    return (__nv_bfloat16*)p;
}

static void gemm_nn128(const float* A, const float* B, float* C, int M, int Nn, int K) {
    dim3 grid(Nn / 128, M / 128);
    sgemm_kernel<128, 128, 16, 8, 8, false><<<grid, 256>>>(A, B, C, M, Nn, K, nullptr);
}

static void thin_gemm(const float* A, const float* B, float* out, int Nn, int act,
                      float* part) {
    dim3 grid(1, kS / 128, kKSPLIT);
    if (Nn == 128)
        gemm_splitk_kernel<128, 128, 16, 8, 8><<<grid, 256>>>(A, B, part, kS, Nn, kD);
    else if (Nn == 64)
        gemm_splitk_kernel<128, 64, 16, 8, 4><<<grid, 256>>>(A, B, part, kS, Nn, kD);
    else
        gemm_splitk_kernel<128, 32, 16, 8, 4><<<grid, 128>>>(A, B, part, kS, Nn, kD);
    int MN = kS * Nn;
    splitk_reduce_kernel<<<(MN + 255) / 256, 256>>>(part, out, MN, act);
}

// big NT GEMM on tensor cores: C = A @ W^T (+resid), fp32 in/out, bf16x3 inside
static void big_gemm_tc(const float* A, const float* W, float* C, const float* resid,
                        __nv_bfloat16* ah, __nv_bfloat16* al,
                        __nv_bfloat16* wh, __nv_bfloat16* wl)
{
    int n4 = (int)(kSD / 4);
    split_bf16_kernel<<<n4 / 256, 256>>>((const float4*)A, (__nv_bfloat162*)ah,
                                         (__nv_bfloat162*)al, n4);
    split_bf16_kernel<<<n4 / 256, 256>>>((const float4*)W, (__nv_bfloat162*)wh,
                                         (__nv_bfloat162*)wl, n4);
    cudaFuncSetAttribute(bf16x3_nt_kernel, cudaFuncAttributeMaxDynamicSharedMemorySize, kSMEM);
    dim3 grid(16, 16);
    bf16x3_nt_kernel<<<grid, 256, kSMEM>>>(ah, al, wh, wl, C, resid);
}

extern "C" void kernel_launch(void* const* d_in, const int* in_sizes, int n_in,
                              void* d_out, int out_size)
{
    (void)in_sizes; (void)n_in;
    const float* x      = (const float*)d_in[0];
    const float* st1    = (const float*)d_in[1];
    const float* st2    = (const float*)d_in[2];
    const float* vfirst = (const float*)d_in[3];
    const float* ln1w   = (const float*)d_in[4];
    const float* ln1b   = (const float*)d_in[5];
    const float* m_r    = (const float*)d_in[6];
    const float* m_w    = (const float*)d_in[7];
    const float* m_k    = (const float*)d_in[8];
    const float* m_v    = (const float*)d_in[9];
    const float* m_a    = (const float*)d_in[10];
    const float* m_g    = (const float*)d_in[11];
    const float* Wr     = (const float*)d_in[12];
    const float* Wk     = (const float*)d_in[13];
    const float* Wv     = (const float*)d_in[14];
    const float* Wo     = (const float*)d_in[15];
    const float* w1     = (const float*)d_in[16];
    const float* w2     = (const float*)d_in[17];
    const float* w0     = (const float*)d_in[18];
    const float* a1     = (const float*)d_in[19];
    const float* a2     = (const float*)d_in[20];
    const float* a0     = (const float*)d_in[21];
    const float* g1     = (const float*)d_in[22];
    const float* g2     = (const float*)d_in[23];
    const float* v1     = (const float*)d_in[24];
    const float* v2     = (const float*)d_in[25];
    const float* v0     = (const float*)d_in[26];
    const float* k_k    = (const float*)d_in[27];
    const float* k_a    = (const float*)d_in[28];
    const float* r_k    = (const float*)d_in[29];
    const float* lnxw   = (const float*)d_in[30];
    const float* lnxb   = (const float*)d_in[31];

    float* out = (float*)d_out;
    float* s1out = nullptr;
    float* s2out = nullptr;
    long long total1 = (long long)kSD + kD;
    long long total2 = total1 + (long long)kH * kN * kN;
    if ((long long)out_size >= total1) s1out = out + kSD;
    if ((long long)out_size >= total2) s2out = out + kSD + kD;

    float* p_xn   = getsym(g_xn);
    float* p_xr   = getsym(g_xr);
    float* p_xw   = getsym(g_xw);
    float* p_xk   = getsym(g_xk);
    float* p_xv   = getsym(g_xv);
    float* p_xa   = getsym(g_xa);
    float* p_xg   = getsym(g_xg);
    float* p_r    = getsym(g_r);
    float* p_k    = getsym(g_k);
    float* p_v    = getsym(g_v);
    float* p_a    = getsym(g_a);
    float* p_wdec = getsym(g_wdec);
    float* p_gate = getsym(g_gate);
    float* p_kk   = getsym(g_kk);
    float* p_b    = getsym(g_b);
    float* p_y    = getsym(g_y);
    float* p_opre = getsym(g_opre);
    float* p_tmpD = getsym(g_tmpD);
    float* p_t1   = getsym(g_t1);
    float* p_part = getsym(g_part);
    __nv_bfloat16* p_ah = getsym_bf(g_ah);
    __nv_bfloat16* p_al = getsym_bf(g_al);
    __nv_bfloat16* p_wh = getsym_bf(g_wh);
    __nv_bfloat16* p_wl = getsym_bf(g_wl);

    int ew_blocks = (int)(kSD / 256);

    // 1. LN + state1_out
    ln_kernel<<<kS, 256>>>(x, ln1w, ln1b, p_xn, s1out);
    // 2. token shift + mixes
    shift_mix_kernel<<<ew_blocks, 256>>>(p_xn, st1, m_r, m_w, m_k, m_v, m_a, m_g);
    // 3. big projections on tensor cores: r/k/v = x? @ W?^T
    big_gemm_tc(p_xr, Wr, p_r, nullptr, p_ah, p_al, p_wh, p_wl);
    big_gemm_tc(p_xk, Wk, p_k, nullptr, p_ah, p_al, p_wh, p_wl);
    big_gemm_tc(p_xv, Wv, p_v, nullptr, p_ah, p_al, p_wh, p_wl);
    // 4a. gate chain: sigmoid(xg@g1)@g2
    thin_gemm(p_xg, g1, p_t1, 128, /*sigmoid*/1, p_part);
    gemm_nn128(p_t1, g2, p_gate, kS, kD, 128);
    // 4b. a chain: sigmoid(xa@a1@a2 + a0)
    thin_gemm(p_xa, a1, p_t1, 64, 0, p_part);
    gemm_nn128(p_t1, a2, p_tmpD, kS, kD, 64);
    a_epi_kernel<<<ew_blocks, 256>>>(p_tmpD, a0, p_a);
    // 4c. w chain: exp(-0.606531 * sigmoid(tanh(xw@w1)@w2 + w0))
    thin_gemm(p_xw, w1, p_t1, 64, /*tanh*/2, p_part);
    gemm_nn128(p_t1, w2, p_tmpD, kS, kD, 64);
    w_epi_kernel<<<ew_blocks, 256>>>(p_tmpD, w0, p_wdec);
    // 4d. v chain: v += (v_first - v) * sigmoid(xv@v1@v2 + v0)
    thin_gemm(p_xv, v1, p_t1, 32, 0, p_part);
    gemm_nn128(p_t1, v2, p_tmpD, kS, kD, 32);
    v_epi_kernel<<<ew_blocks, 256>>>(p_tmpD, v0, vfirst, p_v);
    // 5. per-(s,h) prep
    prep_kernel<<<(kS * kH) / 8, 256>>>(p_k, p_a, k_k, k_a, p_kk, p_b, p_k);
    // 6. sequential scan + state2_out
    scan2_kernel<<<kH, 256>>>(p_r, p_wdec, p_k, p_v, p_kk, p_b, st2, p_y, s2out);
    // 7. groupnorm + rkv + gate
    post_kernel<<<(kS * kH) / 8, 256>>>(p_y, p_r, p_k, p_v, r_k, lnxw, lnxb, p_gate, p_opre);
    // 8. output projection on tensor cores with residual: out = x + opre @ Wo^T
    big_gemm_tc(p_opre, Wo, out, x, p_ah, p_al, p_wh, p_wl);
}

// round 8
// speedup vs baseline: 1.0108x; 1.0108x over previous
#include <cuda_runtime.h>
#include <cuda_bf16.h>
#include <math.h>
#include <stdint.h>

static constexpr int kS = 2048;
static constexpr int kD = 2048;
static constexpr int kH = 32;
static constexpr int kN = 64;
static constexpr size_t kSD = (size_t)kS * kD;
static constexpr int kKSPLIT = 16;

// ---------------- scratch (device globals; no allocation allowed) ----------------
__device__ float g_xn[kSD];
__device__ float g_xr[kSD];
__device__ float g_xw[kSD];
__device__ float g_xk[kSD];
__device__ float g_xv[kSD];
__device__ float g_xa[kSD];
__device__ float g_xg[kSD];
__device__ float g_r[kSD];
__device__ float g_k[kSD];
__device__ float g_v[kSD];
__device__ float g_a[kSD];
__device__ float g_wdec[kSD];
__device__ float g_gate[kSD];
__device__ float g_kk[kSD];
__device__ float g_b[kSD];
__device__ float g_y[kSD];
__device__ float g_opre[kSD];
__device__ float g_t1[(size_t)kS * 128];
__device__ float g_part[(size_t)kKSPLIT * kS * 128];
// bf16 split buffers for tensor-core GEMMs
__device__ __nv_bfloat16 g_ah[kSD];
__device__ __nv_bfloat16 g_al[kSD];
__device__ __nv_bfloat16 g_wh[kSD];
__device__ __nv_bfloat16 g_wl[kSD];

__device__ __forceinline__ float warp_sum(float v) {
    #pragma unroll
    for (int o = 16; o > 0; o >>= 1) v += __shfl_xor_sync(0xffffffffu, v, o);
    return v;
}

__device__ __forceinline__ float sigmoidf_(float x) { return 1.f / (1.f + expf(-x)); }

// packed f32x2 helpers (FFMA2 — ptxas only emits via explicit PTX)
__device__ __forceinline__ float2 ffma2(float2 a, float2 b, float2 c) {
    float2 d;
    asm("fma.rn.f32x2 %0, %1, %2, %3;"
        : "=l"(reinterpret_cast<unsigned long long&>(d))
        : "l"(reinterpret_cast<unsigned long long&>(a)),
          "l"(reinterpret_cast<unsigned long long&>(b)),
          "l"(reinterpret_cast<unsigned long long&>(c)));
    return d;
}
__device__ __forceinline__ float2 fmul2(float2 a, float2 b) {
    float2 d;
    asm("mul.rn.f32x2 %0, %1, %2;"
        : "=l"(reinterpret_cast<unsigned long long&>(d))
        : "l"(reinterpret_cast<unsigned long long&>(a)),
          "l"(reinterpret_cast<unsigned long long&>(b)));
    return d;
}

// ---------------- mma / ldmatrix / cp.async primitives ----------------
__device__ __forceinline__ uint32_t smem_u32(const void* p) {
    return (uint32_t)__cvta_generic_to_shared(p);
}
__device__ __forceinline__ void cp16(uint32_t dst, const void* src) {
    asm volatile("cp.async.cg.shared.global [%0], [%1], 16;" :: "r"(dst), "l"(src));
}
__device__ __forceinline__ void cp_commit() {
    asm volatile("cp.async.commit_group;" ::: "memory");
}
template<int N>
__device__ __forceinline__ void cp_wait() {
    asm volatile("cp.async.wait_group %0;" :: "n"(N) : "memory");
}
__device__ __forceinline__ void ldsm_x4(uint32_t* r, uint32_t addr) {
    asm volatile("ldmatrix.sync.aligned.m8n8.x4.shared.b16 {%0,%1,%2,%3}, [%4];"
                 : "=r"(r[0]), "=r"(r[1]), "=r"(r[2]), "=r"(r[3]) : "r"(addr));
}
__device__ __forceinline__ void mma_bf16(float* c, const uint32_t* a, uint32_t b0, uint32_t b1) {
    asm volatile("mma.sync.aligned.m16n8k16.row.col.f32.bf16.bf16.f32 "
                 "{%0,%1,%2,%3}, {%4,%5,%6,%7}, {%8,%9}, {%0,%1,%2,%3};"
                 : "+f"(c[0]), "+f"(c[1]), "+f"(c[2]), "+f"(c[3])
                 : "r"(a[0]), "r"(a[1]), "r"(a[2]), "r"(a[3]), "r"(b0), "r"(b1));
}

// ---------------- fp32 -> (hi, lo) bf16 split ----------------
__global__ void split_bf16_kernel(const float4* __restrict__ src,
                                  __nv_bfloat162* __restrict__ hi,
                                  __nv_bfloat162* __restrict__ lo, int n4)
{
    int i = blockIdx.x * blockDim.x + threadIdx.x;
    if (i >= n4) return;
    float4 v = src[i];
    __nv_bfloat16 h0 = __float2bfloat16_rn(v.x);
    __nv_bfloat16 h1 = __float2bfloat16_rn(v.y);
    __nv_bfloat16 h2 = __float2bfloat16_rn(v.z);
    __nv_bfloat16 h3 = __float2bfloat16_rn(v.w);
    __nv_bfloat16 l0 = __float2bfloat16_rn(v.x - __bfloat162float(h0));
    __nv_bfloat16 l1 = __float2bfloat16_rn(v.y - __bfloat162float(h1));
    __nv_bfloat16 l2 = __float2bfloat16_rn(v.z - __bfloat162float(h2));
    __nv_bfloat16 l3 = __float2bfloat16_rn(v.w - __bfloat162float(h3));
    hi[2 * i + 0] = __nv_bfloat162(h0, h1);
    hi[2 * i + 1] = __nv_bfloat162(h2, h3);
    lo[2 * i + 0] = __nv_bfloat162(l0, l1);
    lo[2 * i + 1] = __nv_bfloat162(l2, l3);
}

// ---------------- bf16x3 tensor-core NT GEMM: C = Ah@Bh^T + Ah@Bl^T + Al@Bh^T ----
// fixed M=N=K=2048. Block 128x128, BK=32, 8 warps (warp tile 64x32), cp.async 2-stage.
static constexpr int kLDB  = 80;      // bytes per smem row (32 bf16 + 8 pad)
static constexpr int kARR  = 128 * kLDB;   // 10240 B per array
static constexpr int kSTG  = 4 * kARR;     // 40960 B per stage
static constexpr int kSMEM = 2 * kSTG;     // 81920 B total

__global__ void __launch_bounds__(256, 1)
bf16x3_nt_kernel(const __nv_bfloat16* __restrict__ Ah, const __nv_bfloat16* __restrict__ Al,
                 const __nv_bfloat16* __restrict__ Bh, const __nv_bfloat16* __restrict__ Bl,
                 float* __restrict__ C, const float* __restrict__ resid)
{
    constexpr int Kk = 2048;
    constexpr int NT = Kk / 32;
    extern __shared__ char sm_raw[];
    uint32_t sbase = smem_u32(sm_raw);

    int tid = threadIdx.x, lane = tid & 31, wid = tid >> 5;
    int m0 = blockIdx.y * 128, n0 = blockIdx.x * 128;
    int wm = (wid >> 2) * 64;   // 0 / 64
    int wn = (wid & 3) * 32;    // 0/32/64/96

    float acc[4][4][4];
    #pragma unroll
    for (int mt = 0; mt < 4; mt++)
        #pragma unroll
        for (int nt = 0; nt < 4; nt++)
            #pragma unroll
            for (int q = 0; q < 4; q++) acc[mt][nt][q] = 0.f;

    int seg = tid & 3;
    int r0 = tid >> 2;   // 0..63
    const char* sAh0 = (const char*)(Ah + (size_t)(m0 + r0) * Kk + seg * 8);
    const char* sAl0 = (const char*)(Al + (size_t)(m0 + r0) * Kk + seg * 8);
    const char* sBh0 = (const char*)(Bh + (size_t)(n0 + r0) * Kk + seg * 8);
    const char* sBl0 = (const char*)(Bl + (size_t)(n0 + r0) * Kk + seg * 8);
    const size_t rstep = (size_t)64 * Kk * 2;   // +64 rows in bytes
    uint32_t d0 = (uint32_t)(r0 * kLDB + seg * 16);
    uint32_t d1 = (uint32_t)((r0 + 64) * kLDB + seg * 16);

    auto issue = [&](int kt) {
        uint32_t sb = sbase + (uint32_t)(kt & 1) * kSTG;
        size_t koff = (size_t)kt * 64;   // 32 bf16 = 64 bytes
        cp16(sb + 0 * kARR + d0, sAh0 + koff);
        cp16(sb + 0 * kARR + d1, sAh0 + rstep + koff);
        cp16(sb + 1 * kARR + d0, sAl0 + koff);
        cp16(sb + 1 * kARR + d1, sAl0 + rstep + koff);
        cp16(sb + 2 * kARR + d0, sBh0 + koff);
        cp16(sb + 2 * kARR + d1, sBh0 + rstep + koff);
        cp16(sb + 3 * kARR + d0, sBl0 + koff);
        cp16(sb + 3 * kARR + d1, sBl0 + rstep + koff);
        cp_commit();
    };

    issue(0);

    int frow = lane & 15;
    uint32_t fcol = (uint32_t)((lane >> 4) * 16);   // byte offset of k-half

    for (int kt = 0; kt < NT; ++kt) {
        if (kt + 1 < NT) { issue(kt + 1); cp_wait<1>(); }
        else             { cp_wait<0>(); }
        __syncthreads();

        uint32_t sb = sbase + (uint32_t)(kt & 1) * kSTG;
        #pragma unroll
        for (int kh = 0; kh < 2; kh++) {
            uint32_t kb = fcol + (uint32_t)(kh * 32);   // + k16 half in bytes
            uint32_t ah[4][4], al[4][4], bh[2][4], bl[2][4];
            #pragma unroll
            for (int mt = 0; mt < 4; mt++) {
                uint32_t ro = (uint32_t)((wm + mt * 16 + frow) * kLDB) + kb;
                ldsm_x4(ah[mt], sb + 0 * kARR + ro);
                ldsm_x4(al[mt], sb + 1 * kARR + ro);
            }
            #pragma unroll
            for (int g = 0; g < 2; g++) {
                uint32_t ro = (uint32_t)((wn + g * 16 + frow) * kLDB) + kb;
                ldsm_x4(bh[g], sb + 2 * kARR + ro);
                ldsm_x4(bl[g], sb + 3 * kARR + ro);
            }
            #pragma unroll
            for (int mt = 0; mt < 4; mt++) {
                #pragma unroll
                for (int nt = 0; nt < 4; nt++) {
                    int g = nt >> 1, hf = nt & 1;
                    mma_bf16(acc[mt][nt], ah[mt], bh[g][hf], bh[g][2 + hf]);
                    mma_bf16(acc[mt][nt], ah[mt], bl[g][hf], bl[g][2 + hf]);
                    mma_bf16(acc[mt][nt], al[mt], bh[g][hf], bh[g][2 + hf]);
                }
            }
        }
        __syncthreads();
    }

    // epilogue
    int crow = lane >> 2;
    int ccol = (lane & 3) * 2;
    #pragma unroll
    for (int mt = 0; mt < 4; mt++) {
        #pragma unroll
        for (int nt = 0; nt < 4; nt++) {
            int row = m0 + wm + mt * 16 + crow;
            int col = n0 + wn + nt * 8 + ccol;
            size_t o0 = (size_t)row * 2048 + col;
            size_t o1 = (size_t)(row + 8) * 2048 + col;
            float2 v0 = make_float2(acc[mt][nt][0], acc[mt][nt][1]);
            float2 v1 = make_float2(acc[mt][nt][2], acc[mt][nt][3]);
            if (resid) {
                const float2 r0v = *(const float2*)(resid + o0);
                const float2 r1v = *(const float2*)(resid + o1);
                v0.x += r0v.x; v0.y += r0v.y;
                v1.x += r1v.x; v1.y += r1v.y;
            }
            *(float2*)(C + o0) = v0;
            *(float2*)(C + o1) = v1;
        }
    }
}

// ---------------- LayerNorm over D per token ----------------
__global__ void ln_kernel(const float* __restrict__ x, const float* __restrict__ w,
                          const float* __restrict__ b, float* __restrict__ xn,
                          float* __restrict__ s1out)
{
    int s = blockIdx.x;
    int tid = threadIdx.x;
    size_t base = (size_t)s * kD;
    float vals[8];
    float sum = 0.f, sq = 0.f;
    #pragma unroll
    for (int i = 0; i < 8; i++) {
        float v = x[base + tid + i * 256];
        vals[i] = v; sum += v; sq += v * v;
    }
    __shared__ float sh1[256], sh2[256];
    sh1[tid] = sum; sh2[tid] = sq;
    __syncthreads();
    for (int off = 128; off > 0; off >>= 1) {
        if (tid < off) { sh1[tid] += sh1[tid + off]; sh2[tid] += sh2[tid + off]; }
        __syncthreads();
    }
    float mean = sh1[0] * (1.f / kD);
    float var  = sh2[0] * (1.f / kD) - mean * mean;
    float rstd = rsqrtf(var + 1e-5f);
    #pragma unroll
    for (int i = 0; i < 8; i++) {
        int d = tid + i * 256;
        float o = (vals[i] - mean) * rstd * w[d] + b[d];
        xn[base + d] = o;
        if (s1out && s == kS - 1) s1out[d] = o;
    }
}

// ---------------- token shift + 6 mixes ----------------
__global__ void shift_mix_kernel(const float* __restrict__ xn, const float* __restrict__ st1,
    const float* __restrict__ mr, const float* __restrict__ mw, const float* __restrict__ mk,
    const float* __restrict__ mv, const float* __restrict__ ma, const float* __restrict__ mg)
{
    size_t idx = (size_t)blockIdx.x * blockDim.x + threadIdx.x;
    if (idx >= kSD) return;
    int d = (int)(idx & (size_t)(kD - 1));
    float cur = xn[idx];
    float past = (idx < (size_t)kD) ? st1[d] : xn[idx - kD];
    float sx = past - cur;
    g_xr[idx] = cur + sx * mr[d];
    g_xw[idx] = cur + sx * mw[d];
    g_xk[idx] = cur + sx * mk[d];
    g_xv[idx] = cur + sx * mv[d];
    g_xa[idx] = cur + sx * ma[d];
    g_xg[idx] = cur + sx * mg[d];
}

// ---------------- generic tiled SGEMM with fused activation epilogue ----------------
// act: 0 none (+resid), 2 sigmoid(acc+bias[n]), 3 exp(-0.606531*sigmoid(acc+bias[n])),
//      4 C[i] = C[i] + (aux[i]-C[i])*sigmoid(acc+bias[n])   (C read-modify-write)
template<int BM, int BN, int BK, int TM, int TN, bool BT>
__global__ void __launch_bounds__((BM/TM)*(BN/TN))
sgemm_kernel(const float* __restrict__ A, const float* __restrict__ B,
             float* __restrict__ C, int M, int Nn, int K,
             const float* __restrict__ resid, int act,
             const float* __restrict__ bias, const float* __restrict__ aux)
{
    constexpr int THREADS = (BM / TM) * (BN / TN);
    __shared__ float As[BK][BM + 4];
    __shared__ float Bs[BK][BN + 4];
    int tid = threadIdx.x;
    int m0 = blockIdx.y * BM;
    int n0 = blockIdx.x * BN;
    int tx = tid % (BN / TN);
    int ty = tid / (BN / TN);
    float acc[TM][TN];
    #pragma unroll
    for (int i = 0; i < TM; i++)
        #pragma unroll
        for (int j = 0; j < TN; j++) acc[i][j] = 0.f;

    constexpr int KQ = BK / 4;
    constexpr int A_F4 = BM * BK / 4;
    constexpr int A_PER = A_F4 / THREADS;
    static_assert(A_F4 % THREADS == 0, "A load");
    constexpr int B_F4 = BN * BK / 4;
    constexpr int B_PER = B_F4 / THREADS;
    static_assert(B_F4 % THREADS == 0, "B load");

    for (int k0 = 0; k0 < K; k0 += BK) {
        #pragma unroll
        for (int i = 0; i < A_PER; i++) {
            int e = tid + i * THREADS;
            int row = e / KQ, kq = e % KQ;
            float4 v = *(const float4*)&A[(size_t)(m0 + row) * K + k0 + kq * 4];
            As[kq * 4 + 0][row] = v.x; As[kq * 4 + 1][row] = v.y;
            As[kq * 4 + 2][row] = v.z; As[kq * 4 + 3][row] = v.w;
        }
        if (BT) {
            #pragma unroll
            for (int i = 0; i < B_PER; i++) {
                int e = tid + i * THREADS;
                int row = e / KQ, kq = e % KQ;
                float4 v = *(const float4*)&B[(size_t)(n0 + row) * K + k0 + kq * 4];
                Bs[kq * 4 + 0][row] = v.x; Bs[kq * 4 + 1][row] = v.y;
                Bs[kq * 4 + 2][row] = v.z; Bs[kq * 4 + 3][row] = v.w;
            }
        } else {
            constexpr int NQ = BN / 4;
            #pragma unroll
            for (int i = 0; i < B_PER; i++) {
                int e = tid + i * THREADS;
                int row = e / NQ, nq = e % NQ;
                float4 v = *(const float4*)&B[(size_t)(k0 + row) * Nn + n0 + nq * 4];
                *(float4*)&Bs[row][nq * 4] = v;
            }
        }
        __syncthreads();
        #pragma unroll
        for (int k = 0; k < BK; k++) {
            float af[TM], bf[TN];
            #pragma unroll
            for (int i = 0; i < TM; i++) af[i] = As[k][ty * TM + i];
            #pragma unroll
            for (int j = 0; j < TN; j++) bf[j] = Bs[k][tx * TN + j];
            #pragma unroll
            for (int i = 0; i < TM; i++)
                #pragma unroll
                for (int j = 0; j < TN; j++)
                    acc[i][j] += af[i] * bf[j];
        }
        __syncthreads();
    }
    #pragma unroll
    for (int i = 0; i < TM; i++) {
        size_t rowoff = (size_t)(m0 + ty * TM + i) * Nn + n0 + tx * TN;
        #pragma unroll
        for (int j = 0; j < TN; j++) {
            float v = acc[i][j];
            int col = n0 + tx * TN + j;
            size_t off = rowoff + j;
            if (act == 0) {
                if (resid) v += resid[off];
                C[off] = v;
            } else if (act == 2) {
                C[off] = sigmoidf_(v + bias[col]);
            } else if (act == 3) {
                float sg = sigmoidf_(v + bias[col]);
                C[off] = expf(-0.606531f * sg);
            } else {   // act == 4
                float sg = sigmoidf_(v + bias[col]);
                float vr = C[off];
                C[off] = vr + (aux[off] - vr) * sg;
            }
        }
    }
}

// ---------------- split-K thin GEMM (NN): part[ks][M][N] partials ----------------
template<int BM, int BN, int BK, int TM, int TN>
__global__ void __launch_bounds__((BM/TM)*(BN/TN))
gemm_splitk_kernel(const float* __restrict__ A, const float* __restrict__ B,
                   float* __restrict__ part, int M, int Nn, int K)
{
    constexpr int THREADS = (BM / TM) * (BN / TN);
    __shared__ float As[BK][BM + 4];
    __shared__ float Bs[BK][BN + 4];
    int tid = threadIdx.x;
    int m0 = blockIdx.y * BM;
    int ks = blockIdx.z;
    int kc = K / kKSPLIT;
    int kbeg = ks * kc;
    int tx = tid % (BN / TN);
    int ty = tid / (BN / TN);
    float acc[TM][TN];
    #pragma unroll
    for (int i = 0; i < TM; i++)
        #pragma unroll
        for (int j = 0; j < TN; j++) acc[i][j] = 0.f;

    constexpr int KQ = BK / 4;
    constexpr int A_F4 = BM * BK / 4;
    constexpr int A_PER = A_F4 / THREADS;
    static_assert(A_F4 % THREADS == 0, "A load");
    constexpr int B_F4 = BN * BK / 4;
    constexpr int B_PER = B_F4 / THREADS;
    static_assert(B_F4 % THREADS == 0, "B load");
    constexpr int NQ = BN / 4;

    for (int k0 = kbeg; k0 < kbeg + kc; k0 += BK) {
        #pragma unroll
        for (int i = 0; i < A_PER; i++) {
            int e = tid + i * THREADS;
            int row = e / KQ, kq = e % KQ;
            float4 v = *(const float4*)&A[(size_t)(m0 + row) * K + k0 + kq * 4];
            As[kq * 4 + 0][row] = v.x; As[kq * 4 + 1][row] = v.y;
            As[kq * 4 + 2][row] = v.z; As[kq * 4 + 3][row] = v.w;
        }
        #pragma unroll
        for (int i = 0; i < B_PER; i++) {
            int e = tid + i * THREADS;
            int row = e / NQ, nq = e % NQ;
            float4 v = *(const float4*)&B[(size_t)(k0 + row) * Nn + nq * 4];
            *(float4*)&Bs[row][nq * 4] = v;
        }
        __syncthreads();
        #pragma unroll
        for (int k = 0; k < BK; k++) {
            float af[TM], bf[TN];
            #pragma unroll
            for (int i = 0; i < TM; i++) af[i] = As[k][ty * TM + i];
            #pragma unroll
            for (int j = 0; j < TN; j++) bf[j] = Bs[k][tx * TN + j];
            #pragma unroll
            for (int i = 0; i < TM; i++)
                #pragma unroll
                for (int j = 0; j < TN; j++)
                    acc[i][j] += af[i] * bf[j];
        }
        __syncthreads();
    }
    float* pbase = part + (size_t)ks * M * Nn;
    #pragma unroll
    for (int i = 0; i < TM; i++) {
        size_t rowoff = (size_t)(m0 + ty * TM + i) * Nn + tx * TN;
        #pragma unroll
        for (int j = 0; j < TN; j++) pbase[rowoff + j] = acc[i][j];
    }
}

// act: 0 none, 1 sigmoid, 2 tanh
__global__ void splitk_reduce_kernel(const float* __restrict__ part, float* __restrict__ out,
                                     int MN, int act)
{
    int i = blockIdx.x * blockDim.x + threadIdx.x;
    if (i >= MN) return;
    float s = 0.f;
    #pragma unroll
    for (int ks = 0; ks < kKSPLIT; ks++) s += part[(size_t)ks * MN + i];
    if (act == 1) s = sigmoidf_(s);
    else if (act == 2) s = tanhf(s);
    out[i] = s;
}

// ---------------- per-(s,h) prep: kk normalize, b, k-mod ----------------
__global__ void prep_kernel(const float* __restrict__ k_in, const float* __restrict__ a,
                            const float* __restrict__ k_k, const float* __restrict__ k_a,
                            float* __restrict__ kk_out, float* __restrict__ b_out,
                            float* __restrict__ k_out)
{
    int gwarp = (int)((blockIdx.x * (size_t)blockDim.x + threadIdx.x) >> 5);
    int lane = threadIdx.x & 31;
    if (gwarp >= kS * kH) return;
    int s = gwarp >> 5, h = gwarp & (kH - 1);
    size_t base = (size_t)s * kD + (size_t)h * kN;
    int d0 = h * kN + lane, d1 = d0 + 32;
    float k0 = k_in[base + lane], k1 = k_in[base + lane + 32];
    float kk0 = k0 * k_k[d0], kk1 = k1 * k_k[d1];
    float ss = warp_sum(kk0 * kk0 + kk1 * kk1);
    float inv = 1.f / fmaxf(sqrtf(ss), 1e-12f);
    kk0 *= inv; kk1 *= inv;
    float a0 = a[base + lane], a1 = a[base + lane + 32];
    kk_out[base + lane] = kk0;        kk_out[base + lane + 32] = kk1;
    b_out[base + lane]  = kk0 * a0;   b_out[base + lane + 32]  = kk1 * a1;
    k_out[base + lane]      = k0 * (1.f + (a0 - 1.f) * k_a[d0]);
    k_out[base + lane + 32] = k1 * (1.f + (a1 - 1.f) * k_a[d1]);
}

// ---------------- sequential RWKV7 state scan v2 ----------------
__global__ void __launch_bounds__(256, 1)
scan2_kernel(const float* __restrict__ r, const float* __restrict__ w,
             const float* __restrict__ k, const float* __restrict__ v,
             const float* __restrict__ kk, const float* __restrict__ b,
             const float* __restrict__ st2_in, float* __restrict__ y,
             float* __restrict__ st2_out)
{
    int h = blockIdx.x;
    int tid = threadIdx.x;
    int jq = tid & 3;
    int i = tid >> 2;

    float2 st[8];
    const float2* sin = (const float2*)(st2_in + (size_t)h * kN * kN + (size_t)i * kN + jq * 16);
    #pragma unroll
    for (int m = 0; m < 8; m++) st[m] = sin[m];

    __shared__ __align__(16) float sbuf[2][6][kN];  // order: r, w, k, b, -kk, v

    int arr = tid >> 4;
    int idx = tid & 15;
    const float* src = nullptr;
    if (tid < 96) {
        if (arr == 0) src = r;
        else if (arr == 1) src = w;
        else if (arr == 2) src = k;
        else if (arr == 3) src = b;
        else if (arr == 4) src = kk;
        else src = v;
    }
    size_t gbase = (size_t)h * kN + idx * 4;
    float4 pf = make_float4(0.f, 0.f, 0.f, 0.f);
    if (tid < 96) pf = *(const float4*)(src + gbase);

    for (int t = 0; t < kS; t++) {
        int buf = t & 1;
        if (tid < 96) {
            float4 vv = pf;
            if (arr == 4) { vv.x = -vv.x; vv.y = -vv.y; vv.z = -vv.z; vv.w = -vv.w; }
            *(float4*)&sbuf[buf][arr][idx * 4] = vv;
        }
        __syncthreads();
        if (t + 1 < kS && tid < 96)
            pf = *(const float4*)(src + (size_t)(t + 1) * kD + gbase);

        const float2* r2  = (const float2*)&sbuf[buf][0][jq * 16];
        const float2* w2  = (const float2*)&sbuf[buf][1][jq * 16];
        const float2* k2  = (const float2*)&sbuf[buf][2][jq * 16];
        const float2* b2  = (const float2*)&sbuf[buf][3][jq * 16];
        const float2* na2 = (const float2*)&sbuf[buf][4][jq * 16];

        // two independent accumulation chains for sa (halve dependent-FMA latency)
        float2 acc0 = make_float2(0.f, 0.f), acc1 = make_float2(0.f, 0.f);
        #pragma unroll
        for (int m = 0; m < 4; m++) {
            acc0 = ffma2(st[2 * m + 0], na2[2 * m + 0], acc0);
            acc1 = ffma2(st[2 * m + 1], na2[2 * m + 1], acc1);
        }
        float sa = acc0.x + acc0.y + acc1.x + acc1.y;
        sa += __shfl_xor_sync(0xffffffffu, sa, 1);
        sa += __shfl_xor_sync(0xffffffffu, sa, 2);

        float vi = sbuf[buf][5][i];
        float2 sav = make_float2(sa, sa);
        float2 viv = make_float2(vi, vi);
        float2 y0 = make_float2(0.f, 0.f), y1 = make_float2(0.f, 0.f);
        #pragma unroll
        for (int m = 0; m < 4; m++) {
            float2 t0 = fmul2(viv, k2[2 * m + 0]);
            t0 = ffma2(sav, b2[2 * m + 0], t0);
            float2 s0 = ffma2(st[2 * m + 0], w2[2 * m + 0], t0);
            st[2 * m + 0] = s0;
            y0 = ffma2(s0, r2[2 * m + 0], y0);
            float2 t1 = fmul2(viv, k2[2 * m + 1]);
            t1 = ffma2(sav, b2[2 * m + 1], t1);
            float2 s1 = ffma2(st[2 * m + 1], w2[2 * m + 1], t1);
            st[2 * m + 1] = s1;
            y1 = ffma2(s1, r2[2 * m + 1], y1);
        }
        float yv = y0.x + y0.y + y1.x + y1.y;
        yv += __shfl_xor_sync(0xffffffffu, yv, 1);
        yv += __shfl_xor_sync(0xffffffffu, yv, 2);
        if (jq == 0) y[(size_t)t * kD + (size_t)h * kN + i] = yv;
    }
    if (st2_out) {
        float2* sout = (float2*)(st2_out + (size_t)h * kN * kN + (size_t)i * kN + jq * 16);
        #pragma unroll
        for (int m = 0; m < 8; m++) sout[m] = st[m];
    }
}

// ---------------- groupnorm + rkv + gate epilogue ----------------
__global__ void post_kernel(const float* __restrict__ y, const float* __restrict__ r,
                            const float* __restrict__ k, const float* __restrict__ v,
                            const float* __restrict__ r_k, const float* __restrict__ lnxw,
                            const float* __restrict__ lnxb, const float* __restrict__ gate,
                            float* __restrict__ opre)
{
    int gwarp = (int)((blockIdx.x * (size_t)blockDim.x + threadIdx.x) >> 5);
    int lane = threadIdx.x & 31;
    if (gwarp >= kS * kH) return;
    int s = gwarp >> 5, h = gwarp & (kH - 1);
    size_t base = (size_t)s * kD + (size_t)h * kN;
    int d0 = h * kN + lane, d1 = d0 + 32;
    float y0 = y[base + lane], y1 = y[base + lane + 32];
    float sum = warp_sum(y0 + y1);
    float sq  = warp_sum(y0 * y0 + y1 * y1);
    float mean = sum * (1.f / kN);
    float var  = sq * (1.f / kN) - mean * mean;
    float rstd = rsqrtf(var + 0.00064f);
    float o0 = (y0 - mean) * rstd * lnxw[d0] + lnxb[d0];
    float o1 = (y1 - mean) * rstd * lnxw[d1] + lnxb[d1];
    float r0 = r[base + lane], r1 = r[base + lane + 32];
    float k0 = k[base + lane], k1 = k[base + lane + 32];
    float dot = warp_sum(r0 * k0 * r_k[d0] + r1 * k1 * r_k[d1]);
    float v0 = v[base + lane], v1 = v[base + lane + 32];
    opre[base + lane]      = (o0 + dot * v0) * gate[base + lane];
    opre[base + lane + 32] = (o1 + dot * v1) * gate[base + lane + 32];
}

// ---------------- host side ----------------
static float* getsym(const void* symbol) {
    void* p = nullptr;
    cudaGetSymbolAddress(&p, symbol);
    return (float*)p;
}
static __nv_bfloat16* getsym_bf(const void* symbol) {
    void* p = nullptr;
    cudaGetSymbolAddress(&p, symbol);
    return (__nv_bfloat16*)p;
}

// medium NN GEMM with fused activation epilogue
static void gemm_nn128_act(const float* A, const float* B, float* C, int M, int Nn, int K,
                           int act, const float* bias, const float* aux) {
    dim3 grid(Nn / 128, M / 128);
    sgemm_kernel<128, 128, 16, 8, 8, false><<<grid, 256>>>(A, B, C, M, Nn, K,
                                                           nullptr, act, bias, aux);
}

static void thin_gemm(const float* A, const float* B, float* out, int Nn, int act,
                      float* part) {
    dim3 grid(1, kS / 128, kKSPLIT);
    if (Nn == 128)
        gemm_splitk_kernel<128, 128, 16, 8, 8><<<grid, 256>>>(A, B, part, kS, Nn, kD);
    else if (Nn == 64)
        gemm_splitk_kernel<128, 64, 16, 8, 4><<<grid, 256>>>(A, B, part, kS, Nn, kD);
    else
        gemm_splitk_kernel<128, 32, 16, 8, 4><<<grid, 128>>>(A, B, part, kS, Nn, kD);
    int MN = kS * Nn;
    splitk_reduce_kernel<<<(MN + 255) / 256, 256>>>(part, out, MN, act);
}

// big NT GEMM on tensor cores: C = A @ W^T (+resid), fp32 in/out, bf16x3 inside
static void big_gemm_tc(const float* A, const float* W, float* C, const float* resid,
                        __nv_bfloat16* ah, __nv_bfloat16* al,
                        __nv_bfloat16* wh, __nv_bfloat16* wl)
{
    int n4 = (int)(kSD / 4);
    split_bf16_kernel<<<n4 / 256, 256>>>((const float4*)A, (__nv_bfloat162*)ah,
                                         (__nv_bfloat162*)al, n4);
    split_bf16_kernel<<<n4 / 256, 256>>>((const float4*)W, (__nv_bfloat162*)wh,
                                         (__nv_bfloat162*)wl, n4);
    cudaFuncSetAttribute(bf16x3_nt_kernel, cudaFuncAttributeMaxDynamicSharedMemorySize, kSMEM);
    dim3 grid(16, 16);
    bf16x3_nt_kernel<<<grid, 256, kSMEM>>>(ah, al, wh, wl, C, resid);
}

extern "C" void kernel_launch(void* const* d_in, const int* in_sizes, int n_in,
                              void* d_out, int out_size)
{
    (void)in_sizes; (void)n_in;
    const float* x      = (const float*)d_in[0];
    const float* st1    = (const float*)d_in[1];
    const float* st2    = (const float*)d_in[2];
    const float* vfirst = (const float*)d_in[3];
    const float* ln1w   = (const float*)d_in[4];
    const float* ln1b   = (const float*)d_in[5];
    const float* m_r    = (const float*)d_in[6];
    const float* m_w    = (const float*)d_in[7];
    const float* m_k    = (const float*)d_in[8];
    const float* m_v    = (const float*)d_in[9];
    const float* m_a    = (const float*)d_in[10];
    const float* m_g    = (const float*)d_in[11];
    const float* Wr     = (const float*)d_in[12];
    const float* Wk     = (const float*)d_in[13];
    const float* Wv     = (const float*)d_in[14];
    const float* Wo     = (const float*)d_in[15];
    const float* w1     = (const float*)d_in[16];
    const float* w2     = (const float*)d_in[17];
    const float* w0     = (const float*)d_in[18];
    const float* a1     = (const float*)d_in[19];
    const float* a2     = (const float*)d_in[20];
    const float* a0     = (const float*)d_in[21];
    const float* g1     = (const float*)d_in[22];
    const float* g2     = (const float*)d_in[23];
    const float* v1     = (const float*)d_in[24];
    const float* v2     = (const float*)d_in[25];
    const float* v0     = (const float*)d_in[26];
    const float* k_k    = (const float*)d_in[27];
    const float* k_a    = (const float*)d_in[28];
    const float* r_k    = (const float*)d_in[29];
    const float* lnxw   = (const float*)d_in[30];
    const float* lnxb   = (const float*)d_in[31];

    float* out = (float*)d_out;
    float* s1out = nullptr;
    float* s2out = nullptr;
    long long total1 = (long long)kSD + kD;
    long long total2 = total1 + (long long)kH * kN * kN;
    if ((long long)out_size >= total1) s1out = out + kSD;
    if ((long long)out_size >= total2) s2out = out + kSD + kD;

    float* p_xn   = getsym(g_xn);
    float* p_xr   = getsym(g_xr);
    float* p_xw   = getsym(g_xw);
    float* p_xk   = getsym(g_xk);
    float* p_xv   = getsym(g_xv);
    float* p_xa   = getsym(g_xa);
    float* p_xg   = getsym(g_xg);
    float* p_r    = getsym(g_r);
    float* p_k    = getsym(g_k);
    float* p_v    = getsym(g_v);
    float* p_a    = getsym(g_a);
    float* p_wdec = getsym(g_wdec);
    float* p_gate = getsym(g_gate);
    float* p_kk   = getsym(g_kk);
    float* p_b    = getsym(g_b);
    float* p_y    = getsym(g_y);
    float* p_opre = getsym(g_opre);
    float* p_t1   = getsym(g_t1);
    float* p_part = getsym(g_part);
    __nv_bfloat16* p_ah = getsym_bf(g_ah);
    __nv_bfloat16* p_al = getsym_bf(g_al);
    __nv_bfloat16* p_wh = getsym_bf(g_wh);
    __nv_bfloat16* p_wl = getsym_bf(g_wl);

    int ew_blocks = (int)(kSD / 256);

    // 1. LN + state1_out
    ln_kernel<<<kS, 256>>>(x, ln1w, ln1b, p_xn, s1out);
    // 2. token shift + mixes
    shift_mix_kernel<<<ew_blocks, 256>>>(p_xn, st1, m_r, m_w, m_k, m_v, m_a, m_g);
    // 3. big projections on tensor cores: r/k/v = x? @ W?^T
    big_gemm_tc(p_xr, Wr, p_r, nullptr, p_ah, p_al, p_wh, p_wl);
    big_gemm_tc(p_xk, Wk, p_k, nullptr, p_ah, p_al, p_wh, p_wl);
    big_gemm_tc(p_xv, Wv, p_v, nullptr, p_ah, p_al, p_wh, p_wl);
    // 4a. gate chain: sigmoid(xg@g1)@g2
    thin_gemm(p_xg, g1, p_t1, 128, /*sigmoid*/1, p_part);
    gemm_nn128_act(p_t1, g2, p_gate, kS, kD, 128, 0, nullptr, nullptr);
    // 4b. a chain: a = sigmoid(xa@a1@a2 + a0)  (fused epilogue)
    thin_gemm(p_xa, a1, p_t1, 64, 0, p_part);
    gemm_nn128_act(p_t1, a2, p_a, kS, kD, 64, 2, a0, nullptr);
    // 4c. w chain: wdec = exp(-0.606531*sigmoid(tanh(xw@w1)@w2 + w0))  (fused)
    thin_gemm(p_xw, w1, p_t1, 64, /*tanh*/2, p_part);
    gemm_nn128_act(p_t1, w2, p_wdec, kS, kD, 64, 3, w0, nullptr);
    // 4d. v chain: v += (vfirst - v)*sigmoid(xv@v1@v2 + v0)  (fused RMW)
    thin_gemm(p_xv, v1, p_t1, 32, 0, p_part);
    gemm_nn128_act(p_t1, v2, p_v, kS, kD, 32, 4, v0, vfirst);
    // 5. per-(s,h) prep
    prep_kernel<<<(kS * kH) / 8, 256>>>(p_k, p_a, k_k, k_a, p_kk, p_b, p_k);
    // 6. sequential scan + state2_out
    scan2_kernel<<<kH, 256>>>(p_r, p_wdec, p_k, p_v, p_kk, p_b, st2, p_y, s2out);
    // 7. groupnorm + rkv + gate
    post_kernel<<<(kS * kH) / 8, 256>>>(p_y, p_r, p_k, p_v, r_k, lnxw, lnxb, p_gate, p_opre);
    // 8. output projection on tensor cores with residual: out = x + opre @ Wo^T
    big_gemm_tc(p_opre, Wo, out, x, p_ah, p_al, p_wh, p_wl);
}

// round 9
// speedup vs baseline: 1.0334x; 1.0224x over previous
#include <cuda_runtime.h>
#include <cuda_bf16.h>
#include <math.h>
#include <stdint.h>

static constexpr int kS = 2048;
static constexpr int kD = 2048;
static constexpr int kH = 32;
static constexpr int kN = 64;
static constexpr size_t kSD = (size_t)kS * kD;
static constexpr int kKSPLIT = 16;

// ---------------- scratch (device globals; no allocation allowed) ----------------
__device__ float g_xn[kSD];
__device__ float g_xr[kSD];
__device__ float g_xw[kSD];
__device__ float g_xk[kSD];
__device__ float g_xv[kSD];
__device__ float g_xa[kSD];
__device__ float g_xg[kSD];
__device__ float g_r[kSD];
__device__ float g_k[kSD];
__device__ float g_v[kSD];
__device__ float g_a[kSD];
__device__ float g_wdec[kSD];
__device__ float g_gate[kSD];
__device__ float g_kk[kSD];
__device__ float g_b[kSD];
__device__ float g_y[kSD];
__device__ float g_opre[kSD];
__device__ float g_t1[(size_t)kS * 128];
__device__ float g_part[(size_t)kKSPLIT * kS * 128];
// bf16 split buffers for tensor-core GEMMs
__device__ __nv_bfloat16 g_ah[kSD];
__device__ __nv_bfloat16 g_al[kSD];
__device__ __nv_bfloat16 g_wh[kSD];
__device__ __nv_bfloat16 g_wl[kSD];

__device__ __forceinline__ float warp_sum(float v) {
    #pragma unroll
    for (int o = 16; o > 0; o >>= 1) v += __shfl_xor_sync(0xffffffffu, v, o);
    return v;
}

__device__ __forceinline__ float sigmoidf_(float x) { return 1.f / (1.f + expf(-x)); }

// packed f32x2 helpers (FFMA2 — ptxas only emits via explicit PTX)
__device__ __forceinline__ float2 ffma2(float2 a, float2 b, float2 c) {
    float2 d;
    asm("fma.rn.f32x2 %0, %1, %2, %3;"
        : "=l"(reinterpret_cast<unsigned long long&>(d))
        : "l"(reinterpret_cast<unsigned long long&>(a)),
          "l"(reinterpret_cast<unsigned long long&>(b)),
          "l"(reinterpret_cast<unsigned long long&>(c)));
    return d;
}
__device__ __forceinline__ float2 fmul2(float2 a, float2 b) {
    float2 d;
    asm("mul.rn.f32x2 %0, %1, %2;"
        : "=l"(reinterpret_cast<unsigned long long&>(d))
        : "l"(reinterpret_cast<unsigned long long&>(a)),
          "l"(reinterpret_cast<unsigned long long&>(b)));
    return d;
}

// ---------------- mma / ldmatrix / cp.async primitives ----------------
__device__ __forceinline__ uint32_t smem_u32(const void* p) {
    return (uint32_t)__cvta_generic_to_shared(p);
}
__device__ __forceinline__ void cp16(uint32_t dst, const void* src) {
    asm volatile("cp.async.cg.shared.global [%0], [%1], 16;" :: "r"(dst), "l"(src));
}
__device__ __forceinline__ void cp_commit() {
    asm volatile("cp.async.commit_group;" ::: "memory");
}
template<int N>
__device__ __forceinline__ void cp_wait() {
    asm volatile("cp.async.wait_group %0;" :: "n"(N) : "memory");
}
__device__ __forceinline__ void ldsm_x4(uint32_t* r, uint32_t addr) {
    asm volatile("ldmatrix.sync.aligned.m8n8.x4.shared.b16 {%0,%1,%2,%3}, [%4];"
                 : "=r"(r[0]), "=r"(r[1]), "=r"(r[2]), "=r"(r[3]) : "r"(addr));
}
__device__ __forceinline__ void mma_bf16(float* c, const uint32_t* a, uint32_t b0, uint32_t b1) {
    asm volatile("mma.sync.aligned.m16n8k16.row.col.f32.bf16.bf16.f32 "
                 "{%0,%1,%2,%3}, {%4,%5,%6,%7}, {%8,%9}, {%0,%1,%2,%3};"
                 : "+f"(c[0]), "+f"(c[1]), "+f"(c[2]), "+f"(c[3])
                 : "r"(a[0]), "r"(a[1]), "r"(a[2]), "r"(a[3]), "r"(b0), "r"(b1));
}

// ---------------- fp32 -> (hi, lo) bf16 split ----------------
__global__ void split_bf16_kernel(const float4* __restrict__ src,
                                  __nv_bfloat162* __restrict__ hi,
                                  __nv_bfloat162* __restrict__ lo, int n4)
{
    int i = blockIdx.x * blockDim.x + threadIdx.x;
    if (i >= n4) return;
    float4 v = src[i];
    __nv_bfloat16 h0 = __float2bfloat16_rn(v.x);
    __nv_bfloat16 h1 = __float2bfloat16_rn(v.y);
    __nv_bfloat16 h2 = __float2bfloat16_rn(v.z);
    __nv_bfloat16 h3 = __float2bfloat16_rn(v.w);
    __nv_bfloat16 l0 = __float2bfloat16_rn(v.x - __bfloat162float(h0));
    __nv_bfloat16 l1 = __float2bfloat16_rn(v.y - __bfloat162float(h1));
    __nv_bfloat16 l2 = __float2bfloat16_rn(v.z - __bfloat162float(h2));
    __nv_bfloat16 l3 = __float2bfloat16_rn(v.w - __bfloat162float(h3));
    hi[2 * i + 0] = __nv_bfloat162(h0, h1);
    hi[2 * i + 1] = __nv_bfloat162(h2, h3);
    lo[2 * i + 0] = __nv_bfloat162(l0, l1);
    lo[2 * i + 1] = __nv_bfloat162(l2, l3);
}

// ---------------- transpose + split: W[K][N] f32 -> Th/Tl[N][K] bf16 (K<=128, K%8==0) --
__global__ void tsplit_kernel(const float* __restrict__ W,
                              __nv_bfloat16* __restrict__ Th, __nv_bfloat16* __restrict__ Tl,
                              int K, int N)
{
    __shared__ float sm[128][33];
    int n0 = blockIdx.x * 32;
    int tid = threadIdx.x;
    int tn = tid & 31, tk = tid >> 5;
    for (int k = tk; k < K; k += 8)
        sm[k][tn] = W[(size_t)k * N + n0 + tn];
    __syncthreads();
    int rn = tid >> 3;
    int kper = K >> 3;
    int rk0 = (tid & 7) * kper;
    for (int q = 0; q < kper; q++) {
        int k = rk0 + q;
        float v = sm[k][rn];
        __nv_bfloat16 h = __float2bfloat16_rn(v);
        __nv_bfloat16 l = __float2bfloat16_rn(v - __bfloat162float(h));
        Th[(size_t)(n0 + rn) * K + k] = h;
        Tl[(size_t)(n0 + rn) * K + k] = l;
    }
}

// ---------------- bf16x3 tensor-core NT GEMM (runtime K): ----------------------------
// C[2048-wide] = Ah@Bh^T + Ah@Bl^T + Al@Bh^T, fp32 out, fused activation epilogue.
// act: 0 none(+resid), 2 sigmoid(acc+bias[n]), 3 exp(-0.606531*sigmoid(acc+bias[n])),
//      4 C = C + (aux-C)*sigmoid(acc+bias[n])
static constexpr int kLDB  = 80;           // bytes per smem row (32 bf16 + 8 pad)
static constexpr int kARR  = 128 * kLDB;   // 10240 B per array
static constexpr int kSTG  = 4 * kARR;     // 40960 B per stage
static constexpr int kSMEM = 2 * kSTG;     // 81920 B total

__global__ void __launch_bounds__(256, 1)
bf16x3_nt_kernel(const __nv_bfloat16* __restrict__ Ah, const __nv_bfloat16* __restrict__ Al,
                 const __nv_bfloat16* __restrict__ Bh, const __nv_bfloat16* __restrict__ Bl,
                 float* __restrict__ C, const float* __restrict__ resid, int K,
                 int act, const float* __restrict__ bias, const float* __restrict__ aux)
{
    const int NT = K >> 5;
    extern __shared__ char sm_raw[];
    uint32_t sbase = smem_u32(sm_raw);

    int tid = threadIdx.x, lane = tid & 31, wid = tid >> 5;
    int m0 = blockIdx.y * 128, n0 = blockIdx.x * 128;
    int wm = (wid >> 2) * 64;   // 0 / 64
    int wn = (wid & 3) * 32;    // 0/32/64/96

    float acc[4][4][4];
    #pragma unroll
    for (int mt = 0; mt < 4; mt++)
        #pragma unroll
        for (int nt = 0; nt < 4; nt++)
            #pragma unroll
            for (int q = 0; q < 4; q++) acc[mt][nt][q] = 0.f;

    int seg = tid & 3;
    int r0 = tid >> 2;   // 0..63
    const char* sAh0 = (const char*)(Ah + (size_t)(m0 + r0) * K + seg * 8);
    const char* sAl0 = (const char*)(Al + (size_t)(m0 + r0) * K + seg * 8);
    const char* sBh0 = (const char*)(Bh + (size_t)(n0 + r0) * K + seg * 8);
    const char* sBl0 = (const char*)(Bl + (size_t)(n0 + r0) * K + seg * 8);
    const size_t rstep = (size_t)64 * K * 2;   // +64 rows in bytes
    uint32_t d0 = (uint32_t)(r0 * kLDB + seg * 16);
    uint32_t d1 = (uint32_t)((r0 + 64) * kLDB + seg * 16);

    auto issue = [&](int kt) {
        uint32_t sb = sbase + (uint32_t)(kt & 1) * kSTG;
        size_t koff = (size_t)kt * 64;   // 32 bf16 = 64 bytes
        cp16(sb + 0 * kARR + d0, sAh0 + koff);
        cp16(sb + 0 * kARR + d1, sAh0 + rstep + koff);
        cp16(sb + 1 * kARR + d0, sAl0 + koff);
        cp16(sb + 1 * kARR + d1, sAl0 + rstep + koff);
        cp16(sb + 2 * kARR + d0, sBh0 + koff);
        cp16(sb + 2 * kARR + d1, sBh0 + rstep + koff);
        cp16(sb + 3 * kARR + d0, sBl0 + koff);
        cp16(sb + 3 * kARR + d1, sBl0 + rstep + koff);
        cp_commit();
    };

    issue(0);

    int frow = lane & 15;
    uint32_t fcol = (uint32_t)((lane >> 4) * 16);   // byte offset of k-half

    for (int kt = 0; kt < NT; ++kt) {
        if (kt + 1 < NT) { issue(kt + 1); cp_wait<1>(); }
        else             { cp_wait<0>(); }
        __syncthreads();

        uint32_t sb = sbase + (uint32_t)(kt & 1) * kSTG;
        #pragma unroll
        for (int kh = 0; kh < 2; kh++) {
            uint32_t kb = fcol + (uint32_t)(kh * 32);   // + k16 half in bytes
            uint32_t ah[4][4], al[4][4], bh[2][4], bl[2][4];
            #pragma unroll
            for (int mt = 0; mt < 4; mt++) {
                uint32_t ro = (uint32_t)((wm + mt * 16 + frow) * kLDB) + kb;
                ldsm_x4(ah[mt], sb + 0 * kARR + ro);
                ldsm_x4(al[mt], sb + 1 * kARR + ro);
            }
            #pragma unroll
            for (int g = 0; g < 2; g++) {
                uint32_t ro = (uint32_t)((wn + g * 16 + frow) * kLDB) + kb;
                ldsm_x4(bh[g], sb + 2 * kARR + ro);
                ldsm_x4(bl[g], sb + 3 * kARR + ro);
            }
            #pragma unroll
            for (int mt = 0; mt < 4; mt++) {
                #pragma unroll
                for (int nt = 0; nt < 4; nt++) {
                    int g = nt >> 1, hf = nt & 1;
                    mma_bf16(acc[mt][nt], ah[mt], bh[g][hf], bh[g][2 + hf]);
                    mma_bf16(acc[mt][nt], ah[mt], bl[g][hf], bl[g][2 + hf]);
                    mma_bf16(acc[mt][nt], al[mt], bh[g][hf], bh[g][2 + hf]);
                }
            }
        }
        __syncthreads();
    }

    // epilogue
    int crow = lane >> 2;
    int ccol = (lane & 3) * 2;
    #pragma unroll
    for (int mt = 0; mt < 4; mt++) {
        #pragma unroll
        for (int nt = 0; nt < 4; nt++) {
            int row = m0 + wm + mt * 16 + crow;
            int col = n0 + wn + nt * 8 + ccol;
            #pragma unroll
            for (int half = 0; half < 2; half++) {
                int rr = row + half * 8;
                size_t off = (size_t)rr * 2048 + col;
                float e0 = acc[mt][nt][half * 2 + 0];
                float e1 = acc[mt][nt][half * 2 + 1];
                if (act == 0) {
                    if (resid) {
                        const float2 rv = *(const float2*)(resid + off);
                        e0 += rv.x; e1 += rv.y;
                    }
                    *(float2*)(C + off) = make_float2(e0, e1);
                } else if (act == 2) {
                    e0 = sigmoidf_(e0 + bias[col]);
                    e1 = sigmoidf_(e1 + bias[col + 1]);
                    *(float2*)(C + off) = make_float2(e0, e1);
                } else if (act == 3) {
                    e0 = expf(-0.606531f * sigmoidf_(e0 + bias[col]));
                    e1 = expf(-0.606531f * sigmoidf_(e1 + bias[col + 1]));
                    *(float2*)(C + off) = make_float2(e0, e1);
                } else {   // act == 4
                    float sg0 = sigmoidf_(e0 + bias[col]);
                    float sg1 = sigmoidf_(e1 + bias[col + 1]);
                    float2 cv = *(const float2*)(C + off);
                    float2 av = *(const float2*)(aux + off);
                    cv.x += (av.x - cv.x) * sg0;
                    cv.y += (av.y - cv.y) * sg1;
                    *(float2*)(C + off) = cv;
                }
            }
        }
    }
}

// ---------------- LayerNorm over D per token ----------------
__global__ void ln_kernel(const float* __restrict__ x, const float* __restrict__ w,
                          const float* __restrict__ b, float* __restrict__ xn,
                          float* __restrict__ s1out)
{
    int s = blockIdx.x;
    int tid = threadIdx.x;
    size_t base = (size_t)s * kD;
    float vals[8];
    float sum = 0.f, sq = 0.f;
    #pragma unroll
    for (int i = 0; i < 8; i++) {
        float v = x[base + tid + i * 256];
        vals[i] = v; sum += v; sq += v * v;
    }
    __shared__ float sh1[256], sh2[256];
    sh1[tid] = sum; sh2[tid] = sq;
    __syncthreads();
    for (int off = 128; off > 0; off >>= 1) {
        if (tid < off) { sh1[tid] += sh1[tid + off]; sh2[tid] += sh2[tid + off]; }
        __syncthreads();
    }
    float mean = sh1[0] * (1.f / kD);
    float var  = sh2[0] * (1.f / kD) - mean * mean;
    float rstd = rsqrtf(var + 1e-5f);
    #pragma unroll
    for (int i = 0; i < 8; i++) {
        int d = tid + i * 256;
        float o = (vals[i] - mean) * rstd * w[d] + b[d];
        xn[base + d] = o;
        if (s1out && s == kS - 1) s1out[d] = o;
    }
}

// ---------------- token shift + 6 mixes ----------------
__global__ void shift_mix_kernel(const float* __restrict__ xn, const float* __restrict__ st1,
    const float* __restrict__ mr, const float* __restrict__ mw, const float* __restrict__ mk,
    const float* __restrict__ mv, const float* __restrict__ ma, const float* __restrict__ mg)
{
    size_t idx = (size_t)blockIdx.x * blockDim.x + threadIdx.x;
    if (idx >= kSD) return;
    int d = (int)(idx & (size_t)(kD - 1));
    float cur = xn[idx];
    float past = (idx < (size_t)kD) ? st1[d] : xn[idx - kD];
    float sx = past - cur;
    g_xr[idx] = cur + sx * mr[d];
    g_xw[idx] = cur + sx * mw[d];
    g_xk[idx] = cur + sx * mk[d];
    g_xv[idx] = cur + sx * mv[d];
    g_xa[idx] = cur + sx * ma[d];
    g_xg[idx] = cur + sx * mg[d];
}

// ---------------- split-K thin GEMM (NN): part[ks][M][N] partials ----------------
template<int BM, int BN, int BK, int TM, int TN>
__global__ void __launch_bounds__((BM/TM)*(BN/TN))
gemm_splitk_kernel(const float* __restrict__ A, const float* __restrict__ B,
                   float* __restrict__ part, int M, int Nn, int K)
{
    constexpr int THREADS = (BM / TM) * (BN / TN);
    __shared__ float As[BK][BM + 4];
    __shared__ float Bs[BK][BN + 4];
    int tid = threadIdx.x;
    int m0 = blockIdx.y * BM;
    int ks = blockIdx.z;
    int kc = K / kKSPLIT;
    int kbeg = ks * kc;
    int tx = tid % (BN / TN);
    int ty = tid / (BN / TN);
    float acc[TM][TN];
    #pragma unroll
    for (int i = 0; i < TM; i++)
        #pragma unroll
        for (int j = 0; j < TN; j++) acc[i][j] = 0.f;

    constexpr int KQ = BK / 4;
    constexpr int A_F4 = BM * BK / 4;
    constexpr int A_PER = A_F4 / THREADS;
    static_assert(A_F4 % THREADS == 0, "A load");
    constexpr int B_F4 = BN * BK / 4;
    constexpr int B_PER = B_F4 / THREADS;
    static_assert(B_F4 % THREADS == 0, "B load");
    constexpr int NQ = BN / 4;

    for (int k0 = kbeg; k0 < kbeg + kc; k0 += BK) {
        #pragma unroll
        for (int i = 0; i < A_PER; i++) {
            int e = tid + i * THREADS;
            int row = e / KQ, kq = e % KQ;
            float4 v = *(const float4*)&A[(size_t)(m0 + row) * K + k0 + kq * 4];
            As[kq * 4 + 0][row] = v.x; As[kq * 4 + 1][row] = v.y;
            As[kq * 4 + 2][row] = v.z; As[kq * 4 + 3][row] = v.w;
        }
        #pragma unroll
        for (int i = 0; i < B_PER; i++) {
            int e = tid + i * THREADS;
            int row = e / NQ, nq = e % NQ;
            float4 v = *(const float4*)&B[(size_t)(k0 + row) * Nn + nq * 4];
            *(float4*)&Bs[row][nq * 4] = v;
        }
        __syncthreads();
        #pragma unroll
        for (int k = 0; k < BK; k++) {
            float af[TM], bf[TN];
            #pragma unroll
            for (int i = 0; i < TM; i++) af[i] = As[k][ty * TM + i];
            #pragma unroll
            for (int j = 0; j < TN; j++) bf[j] = Bs[k][tx * TN + j];
            #pragma unroll
            for (int i = 0; i < TM; i++)
                #pragma unroll
                for (int j = 0; j < TN; j++)
                    acc[i][j] += af[i] * bf[j];
        }
        __syncthreads();
    }
    float* pbase = part + (size_t)ks * M * Nn;
    #pragma unroll
    for (int i = 0; i < TM; i++) {
        size_t rowoff = (size_t)(m0 + ty * TM + i) * Nn + tx * TN;
        #pragma unroll
        for (int j = 0; j < TN; j++) pbase[rowoff + j] = acc[i][j];
    }
}

// act: 0 none, 1 sigmoid, 2 tanh
__global__ void splitk_reduce_kernel(const float* __restrict__ part, float* __restrict__ out,
                                     int MN, int act)
{
    int i = blockIdx.x * blockDim.x + threadIdx.x;
    if (i >= MN) return;
    float s = 0.f;
    #pragma unroll
    for (int ks = 0; ks < kKSPLIT; ks++) s += part[(size_t)ks * MN + i];
    if (act == 1) s = sigmoidf_(s);
    else if (act == 2) s = tanhf(s);
    out[i] = s;
}

// ---------------- per-(s,h) prep: kk normalize, b, k-mod ----------------
__global__ void prep_kernel(const float* __restrict__ k_in, const float* __restrict__ a,
                            const float* __restrict__ k_k, const float* __restrict__ k_a,
                            float* __restrict__ kk_out, float* __restrict__ b_out,
                            float* __restrict__ k_out)
{
    int gwarp = (int)((blockIdx.x * (size_t)blockDim.x + threadIdx.x) >> 5);
    int lane = threadIdx.x & 31;
    if (gwarp >= kS * kH) return;
    int s = gwarp >> 5, h = gwarp & (kH - 1);
    size_t base = (size_t)s * kD + (size_t)h * kN;
    int d0 = h * kN + lane, d1 = d0 + 32;
    float k0 = k_in[base + lane], k1 = k_in[base + lane + 32];
    float kk0 = k0 * k_k[d0], kk1 = k1 * k_k[d1];
    float ss = warp_sum(kk0 * kk0 + kk1 * kk1);
    float inv = 1.f / fmaxf(sqrtf(ss), 1e-12f);
    kk0 *= inv; kk1 *= inv;
    float a0 = a[base + lane], a1 = a[base + lane + 32];
    kk_out[base + lane] = kk0;        kk_out[base + lane + 32] = kk1;
    b_out[base + lane]  = kk0 * a0;   b_out[base + lane + 32]  = kk1 * a1;
    k_out[base + lane]      = k0 * (1.f + (a0 - 1.f) * k_a[d0]);
    k_out[base + lane + 32] = k1 * (1.f + (a1 - 1.f) * k_a[d1]);
}

// ---------------- sequential RWKV7 state scan v3: cp.async ring, depth 9 --------------
// one block per head; 256 threads = 64 i-rows x 4 j-quarters; 16 cols/thread (8 float2)
__global__ void __launch_bounds__(256, 1)
scan3_kernel(const float* __restrict__ r, const float* __restrict__ w,
             const float* __restrict__ k, const float* __restrict__ v,
             const float* __restrict__ kk, const float* __restrict__ b,
             const float* __restrict__ st2_in, float* __restrict__ y,
             float* __restrict__ st2_out)
{
    constexpr int RD = 9;                 // ring depth
    constexpr int SLOT = 6 * kN * 4;      // 1536 bytes per slot
    int h = blockIdx.x;
    int tid = threadIdx.x;
    int jq = tid & 3;
    int i = tid >> 2;

    float2 st[8];
    const float2* sin = (const float2*)(st2_in + (size_t)h * kN * kN + (size_t)i * kN + jq * 16);
    #pragma unroll
    for (int m = 0; m < 8; m++) st[m] = sin[m];

    __shared__ __align__(16) float ring[RD][6][kN];   // order: r, w, k, b, kk, v

    // staging: tid<96, arr = tid/16 (0..5), idx = tid%16 -> one float4 per step
    int arr = tid >> 4;
    int idx = tid & 15;
    const float* src = nullptr;
    if (tid < 96) {
        if (arr == 0) src = r;
        else if (arr == 1) src = w;
        else if (arr == 2) src = k;
        else if (arr == 3) src = b;
        else if (arr == 4) src = kk;
        else src = v;
    }
    size_t gbase = (size_t)h * kN + idx * 4;
    uint32_t sdst0 = smem_u32(&ring[0][arr < 6 ? arr : 0][idx * 4]);

    // prologue: issue slots 0..6 (7 commit groups)
    #pragma unroll
    for (int t = 0; t < 7; t++) {
        if (tid < 96) cp16(sdst0 + (uint32_t)t * SLOT, src + (size_t)t * kD + gbase);
        cp_commit();
    }

    int slc = 0;   // t mod RD
    int sli = 7;   // (t+7) mod RD

    for (int t = 0; t < kS; t++) {
        // issue step t+7 into ring slot sli (reuse-safe: depth 9 > drift window 8)
        if (t + 7 < kS) {
            if (tid < 96) cp16(sdst0 + (uint32_t)sli * SLOT, src + (size_t)(t + 7) * kD + gbase);
        }
        cp_commit();
        cp_wait<6>();
        __syncthreads();   // publish slot t (completed by iter t-1's wait)

        const float2* r2  = (const float2*)&ring[slc][0][jq * 16];
        const float2* w2  = (const float2*)&ring[slc][1][jq * 16];
        const float2* k2  = (const float2*)&ring[slc][2][jq * 16];
        const float2* b2  = (const float2*)&ring[slc][3][jq * 16];
        const float2* kk2 = (const float2*)&ring[slc][4][jq * 16];

        // sa = -(sum st*kk), two independent chains
        float2 acc0 = make_float2(0.f, 0.f), acc1 = make_float2(0.f, 0.f);
        #pragma unroll
        for (int m = 0; m < 4; m++) {
            acc0 = ffma2(st[2 * m + 0], kk2[2 * m + 0], acc0);
            acc1 = ffma2(st[2 * m + 1], kk2[2 * m + 1], acc1);
        }
        float sa = acc0.x + acc0.y + acc1.x + acc1.y;
        sa += __shfl_xor_sync(0xffffffffu, sa, 1);
        sa += __shfl_xor_sync(0xffffffffu, sa, 2);
        sa = -sa;

        float vi = ring[slc][5][i];
        float2 sav = make_float2(sa, sa);
        float2 viv = make_float2(vi, vi);
        float2 y0 = make_float2(0.f, 0.f), y1 = make_float2(0.f, 0.f);
        #pragma unroll
        for (int m = 0; m < 4; m++) {
            float2 t0 = fmul2(viv, k2[2 * m + 0]);
            t0 = ffma2(sav, b2[2 * m + 0], t0);
            float2 s0 = ffma2(st[2 * m + 0], w2[2 * m + 0], t0);
            st[2 * m + 0] = s0;
            y0 = ffma2(s0, r2[2 * m + 0], y0);
            float2 t1 = fmul2(viv, k2[2 * m + 1]);
            t1 = ffma2(sav, b2[2 * m + 1], t1);
            float2 s1 = ffma2(st[2 * m + 1], w2[2 * m + 1], t1);
            st[2 * m + 1] = s1;
            y1 = ffma2(s1, r2[2 * m + 1], y1);
        }
        float yv = y0.x + y0.y + y1.x + y1.y;
        yv += __shfl_xor_sync(0xffffffffu, yv, 1);
        yv += __shfl_xor_sync(0xffffffffu, yv, 2);
        if (jq == 0) y[(size_t)t * kD + (size_t)h * kN + i] = yv;

        if (++slc == RD) slc = 0;
        if (++sli == RD) sli = 0;
    }
    if (st2_out) {
        float2* sout = (float2*)(st2_out + (size_t)h * kN * kN + (size_t)i * kN + jq * 16);
        #pragma unroll
        for (int m = 0; m < 8; m++) sout[m] = st[m];
    }
}

// ---------------- groupnorm + rkv + gate epilogue ----------------
__global__ void post_kernel(const float* __restrict__ y, const float* __restrict__ r,
                            const float* __restrict__ k, const float* __restrict__ v,
                            const float* __restrict__ r_k, const float* __restrict__ lnxw,
                            const float* __restrict__ lnxb, const float* __restrict__ gate,
                            float* __restrict__ opre)
{
    int gwarp = (int)((blockIdx.x * (size_t)blockDim.x + threadIdx.x) >> 5);
    int lane = threadIdx.x & 31;
    if (gwarp >= kS * kH) return;
    int s = gwarp >> 5, h = gwarp & (kH - 1);
    size_t base = (size_t)s * kD + (size_t)h * kN;
    int d0 = h * kN + lane, d1 = d0 + 32;
    float y0 = y[base + lane], y1 = y[base + lane + 32];
    float sum = warp_sum(y0 + y1);
    float sq  = warp_sum(y0 * y0 + y1 * y1);
    float mean = sum * (1.f / kN);
    float var  = sq * (1.f / kN) - mean * mean;
    float rstd = rsqrtf(var + 0.00064f);
    float o0 = (y0 - mean) * rstd * lnxw[d0] + lnxb[d0];
    float o1 = (y1 - mean) * rstd * lnxw[d1] + lnxb[d1];
    float r0 = r[base + lane], r1 = r[base + lane + 32];
    float k0 = k[base + lane], k1 = k[base + lane + 32];
    float dot = warp_sum(r0 * k0 * r_k[d0] + r1 * k1 * r_k[d1]);
    float v0 = v[base + lane], v1 = v[base + lane + 32];
    opre[base + lane]      = (o0 + dot * v0) * gate[base + lane];
    opre[base + lane + 32] = (o1 + dot * v1) * gate[base + lane + 32];
}

// ---------------- host side ----------------
static float* getsym(const void* symbol) {
    void* p = nullptr;
    cudaGetSymbolAddress(&p, symbol);
    return (float*)p;
}
static __nv_bfloat16* getsym_bf(const void* symbol) {
    void* p = nullptr;
    cudaGetSymbolAddress(&p, symbol);
    return (__nv_bfloat16*)p;
}

static void thin_gemm(const float* A, const float* B, float* out, int Nn, int act,
                      float* part) {
    dim3 grid(1, kS / 128, kKSPLIT);
    if (Nn == 128)
        gemm_splitk_kernel<128, 128, 16, 8, 8><<<grid, 256>>>(A, B, part, kS, Nn, kD);
    else if (Nn == 64)
        gemm_splitk_kernel<128, 64, 16, 8, 4><<<grid, 256>>>(A, B, part, kS, Nn, kD);
    else
        gemm_splitk_kernel<128, 32, 16, 8, 4><<<grid, 128>>>(A, B, part, kS, Nn, kD);
    int MN = kS * Nn;
    splitk_reduce_kernel<<<(MN + 255) / 256, 256>>>(part, out, MN, act);
}

// big NT GEMM on tensor cores: C = A @ W^T (+resid), fp32 in/out, bf16x3 inside
static void big_gemm_tc(const float* A, const float* W, float* C, const float* resid,
                        __nv_bfloat16* ah, __nv_bfloat16* al,
                        __nv_bfloat16* wh, __nv_bfloat16* wl)
{
    int n4 = (int)(kSD / 4);
    split_bf16_kernel<<<n4 / 256, 256>>>((const float4*)A, (__nv_bfloat162*)ah,
                                         (__nv_bfloat162*)al, n4);
    split_bf16_kernel<<<n4 / 256, 256>>>((const float4*)W, (__nv_bfloat162*)wh,
                                         (__nv_bfloat162*)wl, n4);
    cudaFuncSetAttribute(bf16x3_nt_kernel, cudaFuncAttributeMaxDynamicSharedMemorySize, kSMEM);
    dim3 grid(16, 16);
    bf16x3_nt_kernel<<<grid, 256, kSMEM>>>(ah, al, wh, wl, C, resid, kD,
                                           0, nullptr, nullptr);
}

// medium NN GEMM on tensor cores: C = A[S,K] @ W[K,2048] with fused activation
static void med_gemm_tc(const float* A, const float* W, float* C, int K,
                        int act, const float* bias, const float* aux,
                        __nv_bfloat16* ah, __nv_bfloat16* al,
                        __nv_bfloat16* wh, __nv_bfloat16* wl)
{
    int n4 = kS * K / 4;
    split_bf16_kernel<<<(n4 + 255) / 256, 256>>>((const float4*)A, (__nv_bfloat162*)ah,
                                                 (__nv_bfloat162*)al, n4);
    tsplit_kernel<<<kD / 32, 256>>>(W, wh, wl, K, kD);
    cudaFuncSetAttribute(bf16x3_nt_kernel, cudaFuncAttributeMaxDynamicSharedMemorySize, kSMEM);
    dim3 grid(16, 16);
    bf16x3_nt_kernel<<<grid, 256, kSMEM>>>(ah, al, wh, wl, C, nullptr, K,
                                           act, bias, aux);
}

extern "C" void kernel_launch(void* const* d_in, const int* in_sizes, int n_in,
                              void* d_out, int out_size)
{
    (void)in_sizes; (void)n_in;
    const float* x      = (const float*)d_in[0];
    const float* st1    = (const float*)d_in[1];
    const float* st2    = (const float*)d_in[2];
    const float* vfirst = (const float*)d_in[3];
    const float* ln1w   = (const float*)d_in[4];
    const float* ln1b   = (const float*)d_in[5];
    const float* m_r    = (const float*)d_in[6];
    const float* m_w    = (const float*)d_in[7];
    const float* m_k    = (const float*)d_in[8];
    const float* m_v    = (const float*)d_in[9];
    const float* m_a    = (const float*)d_in[10];
    const float* m_g    = (const float*)d_in[11];
    const float* Wr     = (const float*)d_in[12];
    const float* Wk     = (const float*)d_in[13];
    const float* Wv     = (const float*)d_in[14];
    const float* Wo     = (const float*)d_in[15];
    const float* w1     = (const float*)d_in[16];
    const float* w2     = (const float*)d_in[17];
    const float* w0     = (const float*)d_in[18];
    const float* a1     = (const float*)d_in[19];
    const float* a2     = (const float*)d_in[20];
    const float* a0     = (const float*)d_in[21];
    const float* g1     = (const float*)d_in[22];
    const float* g2     = (const float*)d_in[23];
    const float* v1     = (const float*)d_in[24];
    const float* v2     = (const float*)d_in[25];
    const float* v0     = (const float*)d_in[26];
    const float* k_k    = (const float*)d_in[27];
    const float* k_a    = (const float*)d_in[28];
    const float* r_k    = (const float*)d_in[29];
    const float* lnxw   = (const float*)d_in[30];
    const float* lnxb   = (const float*)d_in[31];

    float* out = (float*)d_out;
    float* s1out = nullptr;
    float* s2out = nullptr;
    long long total1 = (long long)kSD + kD;
    long long total2 = total1 + (long long)kH * kN * kN;
    if ((long long)out_size >= total1) s1out = out + kSD;
    if ((long long)out_size >= total2) s2out = out + kSD + kD;

    float* p_xn   = getsym(g_xn);
    float* p_xr   = getsym(g_xr);
    float* p_xw   = getsym(g_xw);
    float* p_xk   = getsym(g_xk);
    float* p_xv   = getsym(g_xv);
    float* p_xa   = getsym(g_xa);
    float* p_xg   = getsym(g_xg);
    float* p_r    = getsym(g_r);
    float* p_k    = getsym(g_k);
    float* p_v    = getsym(g_v);
    float* p_a    = getsym(g_a);
    float* p_wdec = getsym(g_wdec);
    float* p_gate = getsym(g_gate);
    float* p_kk   = getsym(g_kk);
    float* p_b    = getsym(g_b);
    float* p_y    = getsym(g_y);
    float* p_opre = getsym(g_opre);
    float* p_t1   = getsym(g_t1);
    float* p_part = getsym(g_part);
    __nv_bfloat16* p_ah = getsym_bf(g_ah);
    __nv_bfloat16* p_al = getsym_bf(g_al);
    __nv_bfloat16* p_wh = getsym_bf(g_wh);
    __nv_bfloat16* p_wl = getsym_bf(g_wl);

    int ew_blocks = (int)(kSD / 256);

    // 1. LN + state1_out
    ln_kernel<<<kS, 256>>>(x, ln1w, ln1b, p_xn, s1out);
    // 2. token shift + mixes
    shift_mix_kernel<<<ew_blocks, 256>>>(p_xn, st1, m_r, m_w, m_k, m_v, m_a, m_g);
    // 3. big projections on tensor cores: r/k/v = x? @ W?^T
    big_gemm_tc(p_xr, Wr, p_r, nullptr, p_ah, p_al, p_wh, p_wl);
    big_gemm_tc(p_xk, Wk, p_k, nullptr, p_ah, p_al, p_wh, p_wl);
    big_gemm_tc(p_xv, Wv, p_v, nullptr, p_ah, p_al, p_wh, p_wl);
    // 4a. gate chain: sigmoid(xg@g1)@g2
    thin_gemm(p_xg, g1, p_t1, 128, /*sigmoid*/1, p_part);
    med_gemm_tc(p_t1, g2, p_gate, 128, 0, nullptr, nullptr, p_ah, p_al, p_wh, p_wl);
    // 4b. a chain: a = sigmoid(xa@a1@a2 + a0)
    thin_gemm(p_xa, a1, p_t1, 64, 0, p_part);
    med_gemm_tc(p_t1, a2, p_a, 64, 2, a0, nullptr, p_ah, p_al, p_wh, p_wl);
    // 4c. w chain: wdec = exp(-0.606531*sigmoid(tanh(xw@w1)@w2 + w0))
    thin_gemm(p_xw, w1, p_t1, 64, /*tanh*/2, p_part);
    med_gemm_tc(p_t1, w2, p_wdec, 64, 3, w0, nullptr, p_ah, p_al, p_wh, p_wl);
    // 4d. v chain: v += (vfirst - v)*sigmoid(xv@v1@v2 + v0)
    thin_gemm(p_xv, v1, p_t1, 32, 0, p_part);
    med_gemm_tc(p_t1, v2, p_v, 32, 4, v0, vfirst, p_ah, p_al, p_wh, p_wl);
    // 5. per-(s,h) prep
    prep_kernel<<<(kS * kH) / 8, 256>>>(p_k, p_a, k_k, k_a, p_kk, p_b, p_k);
    // 6. sequential scan (cp.async ring) + state2_out
    scan3_kernel<<<kH, 256>>>(p_r, p_wdec, p_k, p_v, p_kk, p_b, st2, p_y, s2out);
    // 7. groupnorm + rkv + gate
    post_kernel<<<(kS * kH) / 8, 256>>>(p_y, p_r, p_k, p_v, r_k, lnxw, lnxb, p_gate, p_opre);
    // 8. output projection on tensor cores with residual: out = x + opre @ Wo^T
    big_gemm_tc(p_opre, Wo, out, x, p_ah, p_al, p_wh, p_wl);
}

// round 10
// speedup vs baseline: 1.0338x; 1.0004x over previous
#include <cuda_runtime.h>
#include <cuda_bf16.h>
#include <math.h>
#include <stdint.h>

static constexpr int kS = 2048;
static constexpr int kD = 2048;
static constexpr int kH = 32;
static constexpr int kN = 64;
static constexpr size_t kSD = (size_t)kS * kD;
static constexpr int kKSPLIT = 16;

// ---------------- scratch (device globals; no allocation allowed) ----------------
__device__ float g_xn[kSD];
__device__ float g_xr[kSD];
__device__ float g_xw[kSD];
__device__ float g_xk[kSD];
__device__ float g_xv[kSD];
__device__ float g_xa[kSD];
__device__ float g_xg[kSD];
__device__ float g_r[kSD];
__device__ float g_k[kSD];
__device__ float g_v[kSD];
__device__ float g_a[kSD];
__device__ float g_wdec[kSD];
__device__ float g_gate[kSD];
__device__ float g_kk[kSD];
__device__ float g_b[kSD];
__device__ float g_y[kSD];
__device__ float g_opre[kSD];
__device__ float g_t1[(size_t)kS * 128];
__device__ float g_part[(size_t)kKSPLIT * kS * 128];
// bf16 split buffers for tensor-core GEMMs
__device__ __nv_bfloat16 g_ah[kSD];
__device__ __nv_bfloat16 g_al[kSD];
__device__ __nv_bfloat16 g_wh[kSD];
__device__ __nv_bfloat16 g_wl[kSD];

__device__ __forceinline__ float warp_sum(float v) {
    #pragma unroll
    for (int o = 16; o > 0; o >>= 1) v += __shfl_xor_sync(0xffffffffu, v, o);
    return v;
}

__device__ __forceinline__ float sigmoidf_(float x) { return 1.f / (1.f + expf(-x)); }

// packed f32x2 helpers (FFMA2 — ptxas only emits via explicit PTX)
__device__ __forceinline__ float2 ffma2(float2 a, float2 b, float2 c) {
    float2 d;
    asm("fma.rn.f32x2 %0, %1, %2, %3;"
        : "=l"(reinterpret_cast<unsigned long long&>(d))
        : "l"(reinterpret_cast<unsigned long long&>(a)),
          "l"(reinterpret_cast<unsigned long long&>(b)),
          "l"(reinterpret_cast<unsigned long long&>(c)));
    return d;
}
__device__ __forceinline__ float2 fmul2(float2 a, float2 b) {
    float2 d;
    asm("mul.rn.f32x2 %0, %1, %2;"
        : "=l"(reinterpret_cast<unsigned long long&>(d))
        : "l"(reinterpret_cast<unsigned long long&>(a)),
          "l"(reinterpret_cast<unsigned long long&>(b)));
    return d;
}

// ---------------- mma / ldmatrix / cp.async primitives ----------------
__device__ __forceinline__ uint32_t smem_u32(const void* p) {
    return (uint32_t)__cvta_generic_to_shared(p);
}
__device__ __forceinline__ void cp16(uint32_t dst, const void* src) {
    asm volatile("cp.async.cg.shared.global [%0], [%1], 16;" :: "r"(dst), "l"(src));
}
__device__ __forceinline__ void cp_commit() {
    asm volatile("cp.async.commit_group;" ::: "memory");
}
template<int N>
__device__ __forceinline__ void cp_wait() {
    asm volatile("cp.async.wait_group %0;" :: "n"(N) : "memory");
}
__device__ __forceinline__ void ldsm_x4(uint32_t* r, uint32_t addr) {
    asm volatile("ldmatrix.sync.aligned.m8n8.x4.shared.b16 {%0,%1,%2,%3}, [%4];"
                 : "=r"(r[0]), "=r"(r[1]), "=r"(r[2]), "=r"(r[3]) : "r"(addr));
}
__device__ __forceinline__ void mma_bf16(float* c, const uint32_t* a, uint32_t b0, uint32_t b1) {
    asm volatile("mma.sync.aligned.m16n8k16.row.col.f32.bf16.bf16.f32 "
                 "{%0,%1,%2,%3}, {%4,%5,%6,%7}, {%8,%9}, {%0,%1,%2,%3};"
                 : "+f"(c[0]), "+f"(c[1]), "+f"(c[2]), "+f"(c[3])
                 : "r"(a[0]), "r"(a[1]), "r"(a[2]), "r"(a[3]), "r"(b0), "r"(b1));
}

// ---------------- fp32 -> (hi, lo) bf16 split ----------------
__global__ void split_bf16_kernel(const float4* __restrict__ src,
                                  __nv_bfloat162* __restrict__ hi,
                                  __nv_bfloat162* __restrict__ lo, int n4)
{
    int i = blockIdx.x * blockDim.x + threadIdx.x;
    if (i >= n4) return;
    float4 v = src[i];
    __nv_bfloat16 h0 = __float2bfloat16_rn(v.x);
    __nv_bfloat16 h1 = __float2bfloat16_rn(v.y);
    __nv_bfloat16 h2 = __float2bfloat16_rn(v.z);
    __nv_bfloat16 h3 = __float2bfloat16_rn(v.w);
    __nv_bfloat16 l0 = __float2bfloat16_rn(v.x - __bfloat162float(h0));
    __nv_bfloat16 l1 = __float2bfloat16_rn(v.y - __bfloat162float(h1));
    __nv_bfloat16 l2 = __float2bfloat16_rn(v.z - __bfloat162float(h2));
    __nv_bfloat16 l3 = __float2bfloat16_rn(v.w - __bfloat162float(h3));
    hi[2 * i + 0] = __nv_bfloat162(h0, h1);
    hi[2 * i + 1] = __nv_bfloat162(h2, h3);
    lo[2 * i + 0] = __nv_bfloat162(l0, l1);
    lo[2 * i + 1] = __nv_bfloat162(l2, l3);
}

// ---------------- transpose + split: W[K][N] f32 -> Th/Tl[N][K] bf16 (K<=128, K%8==0) --
__global__ void tsplit_kernel(const float* __restrict__ W,
                              __nv_bfloat16* __restrict__ Th, __nv_bfloat16* __restrict__ Tl,
                              int K, int N)
{
    __shared__ float sm[128][33];
    int n0 = blockIdx.x * 32;
    int tid = threadIdx.x;
    int tn = tid & 31, tk = tid >> 5;
    for (int k = tk; k < K; k += 8)
        sm[k][tn] = W[(size_t)k * N + n0 + tn];
    __syncthreads();
    int rn = tid >> 3;
    int kper = K >> 3;
    int rk0 = (tid & 7) * kper;
    for (int q = 0; q < kper; q++) {
        int k = rk0 + q;
        float v = sm[k][rn];
        __nv_bfloat16 h = __float2bfloat16_rn(v);
        __nv_bfloat16 l = __float2bfloat16_rn(v - __bfloat162float(h));
        Th[(size_t)(n0 + rn) * K + k] = h;
        Tl[(size_t)(n0 + rn) * K + k] = l;
    }
}

// ---------------- bf16x3 tensor-core NT GEMM (runtime K): ----------------------------
// C[2048-wide] = Ah@Bh^T + Ah@Bl^T + Al@Bh^T, fp32 out, fused activation epilogue.
// act: 0 none(+resid), 2 sigmoid(acc+bias[n]), 3 exp(-0.606531*sigmoid(acc+bias[n])),
//      4 C = C + (aux-C)*sigmoid(acc+bias[n])
static constexpr int kLDB  = 80;           // bytes per smem row (32 bf16 + 8 pad)
static constexpr int kARR  = 128 * kLDB;   // 10240 B per array
static constexpr int kSTG  = 4 * kARR;     // 40960 B per stage
static constexpr int kSMEM = 2 * kSTG;     // 81920 B total

__global__ void __launch_bounds__(256, 1)
bf16x3_nt_kernel(const __nv_bfloat16* __restrict__ Ah, const __nv_bfloat16* __restrict__ Al,
                 const __nv_bfloat16* __restrict__ Bh, const __nv_bfloat16* __restrict__ Bl,
                 float* __restrict__ C, const float* __restrict__ resid, int K,
                 int act, const float* __restrict__ bias, const float* __restrict__ aux)
{
    const int NT = K >> 5;
    extern __shared__ char sm_raw[];
    uint32_t sbase = smem_u32(sm_raw);

    int tid = threadIdx.x, lane = tid & 31, wid = tid >> 5;
    int m0 = blockIdx.y * 128, n0 = blockIdx.x * 128;
    int wm = (wid >> 2) * 64;   // 0 / 64
    int wn = (wid & 3) * 32;    // 0/32/64/96

    float acc[4][4][4];
    #pragma unroll
    for (int mt = 0; mt < 4; mt++)
        #pragma unroll
        for (int nt = 0; nt < 4; nt++)
            #pragma unroll
            for (int q = 0; q < 4; q++) acc[mt][nt][q] = 0.f;

    int seg = tid & 3;
    int r0 = tid >> 2;   // 0..63
    const char* sAh0 = (const char*)(Ah + (size_t)(m0 + r0) * K + seg * 8);
    const char* sAl0 = (const char*)(Al + (size_t)(m0 + r0) * K + seg * 8);
    const char* sBh0 = (const char*)(Bh + (size_t)(n0 + r0) * K + seg * 8);
    const char* sBl0 = (const char*)(Bl + (size_t)(n0 + r0) * K + seg * 8);
    const size_t rstep = (size_t)64 * K * 2;   // +64 rows in bytes
    uint32_t d0 = (uint32_t)(r0 * kLDB + seg * 16);
    uint32_t d1 = (uint32_t)((r0 + 64) * kLDB + seg * 16);

    auto issue = [&](int kt) {
        uint32_t sb = sbase + (uint32_t)(kt & 1) * kSTG;
        size_t koff = (size_t)kt * 64;   // 32 bf16 = 64 bytes
        cp16(sb + 0 * kARR + d0, sAh0 + koff);
        cp16(sb + 0 * kARR + d1, sAh0 + rstep + koff);
        cp16(sb + 1 * kARR + d0, sAl0 + koff);
        cp16(sb + 1 * kARR + d1, sAl0 + rstep + koff);
        cp16(sb + 2 * kARR + d0, sBh0 + koff);
        cp16(sb + 2 * kARR + d1, sBh0 + rstep + koff);
        cp16(sb + 3 * kARR + d0, sBl0 + koff);
        cp16(sb + 3 * kARR + d1, sBl0 + rstep + koff);
        cp_commit();
    };

    issue(0);

    int frow = lane & 15;
    uint32_t fcol = (uint32_t)((lane >> 4) * 16);   // byte offset of k-half

    for (int kt = 0; kt < NT; ++kt) {
        if (kt + 1 < NT) { issue(kt + 1); cp_wait<1>(); }
        else             { cp_wait<0>(); }
        __syncthreads();

        uint32_t sb = sbase + (uint32_t)(kt & 1) * kSTG;
        #pragma unroll
        for (int kh = 0; kh < 2; kh++) {
            uint32_t kb = fcol + (uint32_t)(kh * 32);   // + k16 half in bytes
            uint32_t ah[4][4], al[4][4], bh[2][4], bl[2][4];
            #pragma unroll
            for (int mt = 0; mt < 4; mt++) {
                uint32_t ro = (uint32_t)((wm + mt * 16 + frow) * kLDB) + kb;
                ldsm_x4(ah[mt], sb + 0 * kARR + ro);
                ldsm_x4(al[mt], sb + 1 * kARR + ro);
            }
            #pragma unroll
            for (int g = 0; g < 2; g++) {
                uint32_t ro = (uint32_t)((wn + g * 16 + frow) * kLDB) + kb;
                ldsm_x4(bh[g], sb + 2 * kARR + ro);
                ldsm_x4(bl[g], sb + 3 * kARR + ro);
            }
            #pragma unroll
            for (int mt = 0; mt < 4; mt++) {
                #pragma unroll
                for (int nt = 0; nt < 4; nt++) {
                    int g = nt >> 1, hf = nt & 1;
                    mma_bf16(acc[mt][nt], ah[mt], bh[g][hf], bh[g][2 + hf]);
                    mma_bf16(acc[mt][nt], ah[mt], bl[g][hf], bl[g][2 + hf]);
                    mma_bf16(acc[mt][nt], al[mt], bh[g][hf], bh[g][2 + hf]);
                }
            }
        }
        __syncthreads();
    }

    // epilogue
    int crow = lane >> 2;
    int ccol = (lane & 3) * 2;
    #pragma unroll
    for (int mt = 0; mt < 4; mt++) {
        #pragma unroll
        for (int nt = 0; nt < 4; nt++) {
            int row = m0 + wm + mt * 16 + crow;
            int col = n0 + wn + nt * 8 + ccol;
            #pragma unroll
            for (int half = 0; half < 2; half++) {
                int rr = row + half * 8;
                size_t off = (size_t)rr * 2048 + col;
                float e0 = acc[mt][nt][half * 2 + 0];
                float e1 = acc[mt][nt][half * 2 + 1];
                if (act == 0) {
                    if (resid) {
                        const float2 rv = *(const float2*)(resid + off);
                        e0 += rv.x; e1 += rv.y;
                    }
                    *(float2*)(C + off) = make_float2(e0, e1);
                } else if (act == 2) {
                    e0 = sigmoidf_(e0 + bias[col]);
                    e1 = sigmoidf_(e1 + bias[col + 1]);
                    *(float2*)(C + off) = make_float2(e0, e1);
                } else if (act == 3) {
                    e0 = expf(-0.606531f * sigmoidf_(e0 + bias[col]));
                    e1 = expf(-0.606531f * sigmoidf_(e1 + bias[col + 1]));
                    *(float2*)(C + off) = make_float2(e0, e1);
                } else {   // act == 4
                    float sg0 = sigmoidf_(e0 + bias[col]);
                    float sg1 = sigmoidf_(e1 + bias[col + 1]);
                    float2 cv = *(const float2*)(C + off);
                    float2 av = *(const float2*)(aux + off);
                    cv.x += (av.x - cv.x) * sg0;
                    cv.y += (av.y - cv.y) * sg1;
                    *(float2*)(C + off) = cv;
                }
            }
        }
    }
}

// ---------------- LayerNorm over D per token ----------------
__global__ void ln_kernel(const float* __restrict__ x, const float* __restrict__ w,
                          const float* __restrict__ b, float* __restrict__ xn,
                          float* __restrict__ s1out)
{
    int s = blockIdx.x;
    int tid = threadIdx.x;
    size_t base = (size_t)s * kD;
    float vals[8];
    float sum = 0.f, sq = 0.f;
    #pragma unroll
    for (int i = 0; i < 8; i++) {
        float v = x[base + tid + i * 256];
        vals[i] = v; sum += v; sq += v * v;
    }
    __shared__ float sh1[256], sh2[256];
    sh1[tid] = sum; sh2[tid] = sq;
    __syncthreads();
    for (int off = 128; off > 0; off >>= 1) {
        if (tid < off) { sh1[tid] += sh1[tid + off]; sh2[tid] += sh2[tid + off]; }
        __syncthreads();
    }
    float mean = sh1[0] * (1.f / kD);
    float var  = sh2[0] * (1.f / kD) - mean * mean;
    float rstd = rsqrtf(var + 1e-5f);
    #pragma unroll
    for (int i = 0; i < 8; i++) {
        int d = tid + i * 256;
        float o = (vals[i] - mean) * rstd * w[d] + b[d];
        xn[base + d] = o;
        if (s1out && s == kS - 1) s1out[d] = o;
    }
}

// ---------------- token shift + 6 mixes ----------------
__global__ void shift_mix_kernel(const float* __restrict__ xn, const float* __restrict__ st1,
    const float* __restrict__ mr, const float* __restrict__ mw, const float* __restrict__ mk,
    const float* __restrict__ mv, const float* __restrict__ ma, const float* __restrict__ mg)
{
    size_t idx = (size_t)blockIdx.x * blockDim.x + threadIdx.x;
    if (idx >= kSD) return;
    int d = (int)(idx & (size_t)(kD - 1));
    float cur = xn[idx];
    float past = (idx < (size_t)kD) ? st1[d] : xn[idx - kD];
    float sx = past - cur;
    g_xr[idx] = cur + sx * mr[d];
    g_xw[idx] = cur + sx * mw[d];
    g_xk[idx] = cur + sx * mk[d];
    g_xv[idx] = cur + sx * mv[d];
    g_xa[idx] = cur + sx * ma[d];
    g_xg[idx] = cur + sx * mg[d];
}

// ---------------- split-K thin GEMM (NN): part[ks][M][N] partials ----------------
template<int BM, int BN, int BK, int TM, int TN>
__global__ void __launch_bounds__((BM/TM)*(BN/TN))
gemm_splitk_kernel(const float* __restrict__ A, const float* __restrict__ B,
                   float* __restrict__ part, int M, int Nn, int K)
{
    constexpr int THREADS = (BM / TM) * (BN / TN);
    __shared__ float As[BK][BM + 4];
    __shared__ float Bs[BK][BN + 4];
    int tid = threadIdx.x;
    int m0 = blockIdx.y * BM;
    int ks = blockIdx.z;
    int kc = K / kKSPLIT;
    int kbeg = ks * kc;
    int tx = tid % (BN / TN);
    int ty = tid / (BN / TN);
    float acc[TM][TN];
    #pragma unroll
    for (int i = 0; i < TM; i++)
        #pragma unroll
        for (int j = 0; j < TN; j++) acc[i][j] = 0.f;

    constexpr int KQ = BK / 4;
    constexpr int A_F4 = BM * BK / 4;
    constexpr int A_PER = A_F4 / THREADS;
    static_assert(A_F4 % THREADS == 0, "A load");
    constexpr int B_F4 = BN * BK / 4;
    constexpr int B_PER = B_F4 / THREADS;
    static_assert(B_F4 % THREADS == 0, "B load");
    constexpr int NQ = BN / 4;

    for (int k0 = kbeg; k0 < kbeg + kc; k0 += BK) {
        #pragma unroll
        for (int i = 0; i < A_PER; i++) {
            int e = tid + i * THREADS;
            int row = e / KQ, kq = e % KQ;
            float4 v = *(const float4*)&A[(size_t)(m0 + row) * K + k0 + kq * 4];
            As[kq * 4 + 0][row] = v.x; As[kq * 4 + 1][row] = v.y;
            As[kq * 4 + 2][row] = v.z; As[kq * 4 + 3][row] = v.w;
        }
        #pragma unroll
        for (int i = 0; i < B_PER; i++) {
            int e = tid + i * THREADS;
            int row = e / NQ, nq = e % NQ;
            float4 v = *(const float4*)&B[(size_t)(k0 + row) * Nn + nq * 4];
            *(float4*)&Bs[row][nq * 4] = v;
        }
        __syncthreads();
        #pragma unroll
        for (int k = 0; k < BK; k++) {
            float af[TM], bf[TN];
            #pragma unroll
            for (int i = 0; i < TM; i++) af[i] = As[k][ty * TM + i];
            #pragma unroll
            for (int j = 0; j < TN; j++) bf[j] = Bs[k][tx * TN + j];
            #pragma unroll
            for (int i = 0; i < TM; i++)
                #pragma unroll
                for (int j = 0; j < TN; j++)
                    acc[i][j] += af[i] * bf[j];
        }
        __syncthreads();
    }
    float* pbase = part + (size_t)ks * M * Nn;
    #pragma unroll
    for (int i = 0; i < TM; i++) {
        size_t rowoff = (size_t)(m0 + ty * TM + i) * Nn + tx * TN;
        #pragma unroll
        for (int j = 0; j < TN; j++) pbase[rowoff + j] = acc[i][j];
    }
}

// act: 0 none, 1 sigmoid, 2 tanh
__global__ void splitk_reduce_kernel(const float* __restrict__ part, float* __restrict__ out,
                                     int MN, int act)
{
    int i = blockIdx.x * blockDim.x + threadIdx.x;
    if (i >= MN) return;
    float s = 0.f;
    #pragma unroll
    for (int ks = 0; ks < kKSPLIT; ks++) s += part[(size_t)ks * MN + i];
    if (act == 1) s = sigmoidf_(s);
    else if (act == 2) s = tanhf(s);
    out[i] = s;
}

// ---------------- per-(s,h) prep: kk normalize, b, k-mod ----------------
__global__ void prep_kernel(const float* __restrict__ k_in, const float* __restrict__ a,
                            const float* __restrict__ k_k, const float* __restrict__ k_a,
                            float* __restrict__ kk_out, float* __restrict__ b_out,
                            float* __restrict__ k_out)
{
    int gwarp = (int)((blockIdx.x * (size_t)blockDim.x + threadIdx.x) >> 5);
    int lane = threadIdx.x & 31;
    if (gwarp >= kS * kH) return;
    int s = gwarp >> 5, h = gwarp & (kH - 1);
    size_t base = (size_t)s * kD + (size_t)h * kN;
    int d0 = h * kN + lane, d1 = d0 + 32;
    float k0 = k_in[base + lane], k1 = k_in[base + lane + 32];
    float kk0 = k0 * k_k[d0], kk1 = k1 * k_k[d1];
    float ss = warp_sum(kk0 * kk0 + kk1 * kk1);
    float inv = 1.f / fmaxf(sqrtf(ss), 1e-12f);
    kk0 *= inv; kk1 *= inv;
    float a0 = a[base + lane], a1 = a[base + lane + 32];
    kk_out[base + lane] = kk0;        kk_out[base + lane + 32] = kk1;
    b_out[base + lane]  = kk0 * a0;   b_out[base + lane + 32]  = kk1 * a1;
    k_out[base + lane]      = k0 * (1.f + (a0 - 1.f) * k_a[d0]);
    k_out[base + lane + 32] = k1 * (1.f + (a1 - 1.f) * k_a[d1]);
}

// ---------------- sequential RWKV7 state scan v3: cp.async ring, depth 9 --------------
// one block per head; 256 threads = 64 i-rows x 4 j-quarters; 16 cols/thread (8 float2)
__global__ void __launch_bounds__(256, 1)
scan3_kernel(const float* __restrict__ r, const float* __restrict__ w,
             const float* __restrict__ k, const float* __restrict__ v,
             const float* __restrict__ kk, const float* __restrict__ b,
             const float* __restrict__ st2_in, float* __restrict__ y,
             float* __restrict__ st2_out)
{
    constexpr int RD = 9;                 // ring depth
    constexpr int SLOT = 6 * kN * 4;      // 1536 bytes per slot
    int h = blockIdx.x;
    int tid = threadIdx.x;
    int jq = tid & 3;
    int i = tid >> 2;

    float2 st[8];
    const float2* sin = (const float2*)(st2_in + (size_t)h * kN * kN + (size_t)i * kN + jq * 16);
    #pragma unroll
    for (int m = 0; m < 8; m++) st[m] = sin[m];

    __shared__ __align__(16) float ring[RD][6][kN];   // order: r, w, k, b, kk, v

    // staging: tid<96, arr = tid/16 (0..5), idx = tid%16 -> one float4 per step
    int arr = tid >> 4;
    int idx = tid & 15;
    const float* src = nullptr;
    if (tid < 96) {
        if (arr == 0) src = r;
        else if (arr == 1) src = w;
        else if (arr == 2) src = k;
        else if (arr == 3) src = b;
        else if (arr == 4) src = kk;
        else src = v;
    }
    size_t gbase = (size_t)h * kN + idx * 4;
    uint32_t sdst0 = smem_u32(&ring[0][arr < 6 ? arr : 0][idx * 4]);

    // prologue: issue slots 0..6 (7 commit groups)
    #pragma unroll
    for (int t = 0; t < 7; t++) {
        if (tid < 96) cp16(sdst0 + (uint32_t)t * SLOT, src + (size_t)t * kD + gbase);
        cp_commit();
    }

    int slc = 0;   // t mod RD
    int sli = 7;   // (t+7) mod RD

    for (int t = 0; t < kS; t++) {
        // issue step t+7 into ring slot sli (reuse-safe: depth 9 > drift window 8)
        if (t + 7 < kS) {
            if (tid < 96) cp16(sdst0 + (uint32_t)sli * SLOT, src + (size_t)(t + 7) * kD + gbase);
        }
        cp_commit();
        cp_wait<6>();
        __syncthreads();   // publish slot t (completed by iter t-1's wait)

        const float2* r2  = (const float2*)&ring[slc][0][jq * 16];
        const float2* w2  = (const float2*)&ring[slc][1][jq * 16];
        const float2* k2  = (const float2*)&ring[slc][2][jq * 16];
        const float2* b2  = (const float2*)&ring[slc][3][jq * 16];
        const float2* kk2 = (const float2*)&ring[slc][4][jq * 16];

        // sa = -(sum st*kk), two independent chains
        float2 acc0 = make_float2(0.f, 0.f), acc1 = make_float2(0.f, 0.f);
        #pragma unroll
        for (int m = 0; m < 4; m++) {
            acc0 = ffma2(st[2 * m + 0], kk2[2 * m + 0], acc0);
            acc1 = ffma2(st[2 * m + 1], kk2[2 * m + 1], acc1);
        }
        float sa = acc0.x + acc0.y + acc1.x + acc1.y;
        sa += __shfl_xor_sync(0xffffffffu, sa, 1);
        sa += __shfl_xor_sync(0xffffffffu, sa, 2);
        sa = -sa;

        float vi = ring[slc][5][i];
        float2 sav = make_float2(sa, sa);
        float2 viv = make_float2(vi, vi);
        float2 y0 = make_float2(0.f, 0.f), y1 = make_float2(0.f, 0.f);
        #pragma unroll
        for (int m = 0; m < 4; m++) {
            float2 t0 = fmul2(viv, k2[2 * m + 0]);
            t0 = ffma2(sav, b2[2 * m + 0], t0);
            float2 s0 = ffma2(st[2 * m + 0], w2[2 * m + 0], t0);
            st[2 * m + 0] = s0;
            y0 = ffma2(s0, r2[2 * m + 0], y0);
            float2 t1 = fmul2(viv, k2[2 * m + 1]);
            t1 = ffma2(sav, b2[2 * m + 1], t1);
            float2 s1 = ffma2(st[2 * m + 1], w2[2 * m + 1], t1);
            st[2 * m + 1] = s1;
            y1 = ffma2(s1, r2[2 * m + 1], y1);
        }
        float yv = y0.x + y0.y + y1.x + y1.y;
        yv += __shfl_xor_sync(0xffffffffu, yv, 1);
        yv += __shfl_xor_sync(0xffffffffu, yv, 2);
        if (jq == 0) y[(size_t)t * kD + (size_t)h * kN + i] = yv;

        if (++slc == RD) slc = 0;
        if (++sli == RD) sli = 0;
    }
    if (st2_out) {
        float2* sout = (float2*)(st2_out + (size_t)h * kN * kN + (size_t)i * kN + jq * 16);
        #pragma unroll
        for (int m = 0; m < 8; m++) sout[m] = st[m];
    }
}

// ---------------- groupnorm + rkv + gate epilogue ----------------
__global__ void post_kernel(const float* __restrict__ y, const float* __restrict__ r,
                            const float* __restrict__ k, const float* __restrict__ v,
                            const float* __restrict__ r_k, const float* __restrict__ lnxw,
                            const float* __restrict__ lnxb, const float* __restrict__ gate,
                            float* __restrict__ opre)
{
    int gwarp = (int)((blockIdx.x * (size_t)blockDim.x + threadIdx.x) >> 5);
    int lane = threadIdx.x & 31;
    if (gwarp >= kS * kH) return;
    int s = gwarp >> 5, h = gwarp & (kH - 1);
    size_t base = (size_t)s * kD + (size_t)h * kN;
    int d0 = h * kN + lane, d1 = d0 + 32;
    float y0 = y[base + lane], y1 = y[base + lane + 32];
    float sum = warp_sum(y0 + y1);
    float sq  = warp_sum(y0 * y0 + y1 * y1);
    float mean = sum * (1.f / kN);
    float var  = sq * (1.f / kN) - mean * mean;
    float rstd = rsqrtf(var + 0.00064f);
    float o0 = (y0 - mean) * rstd * lnxw[d0] + lnxb[d0];
    float o1 = (y1 - mean) * rstd * lnxw[d1] + lnxb[d1];
    float r0 = r[base + lane], r1 = r[base + lane + 32];
    float k0 = k[base + lane], k1 = k[base + lane + 32];
    float dot = warp_sum(r0 * k0 * r_k[d0] + r1 * k1 * r_k[d1]);
    float v0 = v[base + lane], v1 = v[base + lane + 32];
    opre[base + lane]      = (o0 + dot * v0) * gate[base + lane];
    opre[base + lane + 32] = (o1 + dot * v1) * gate[base + lane + 32];
}

// ---------------- host side ----------------
static float* getsym(const void* symbol) {
    void* p = nullptr;
    cudaGetSymbolAddress(&p, symbol);
    return (float*)p;
}
static __nv_bfloat16* getsym_bf(const void* symbol) {
    void* p = nullptr;
    cudaGetSymbolAddress(&p, symbol);
    return (__nv_bfloat16*)p;
}

static void thin_gemm(const float* A, const float* B, float* out, int Nn, int act,
                      float* part) {
    dim3 grid(1, kS / 128, kKSPLIT);
    if (Nn == 128)
        gemm_splitk_kernel<128, 128, 16, 8, 8><<<grid, 256>>>(A, B, part, kS, Nn, kD);
    else if (Nn == 64)
        gemm_splitk_kernel<128, 64, 16, 8, 4><<<grid, 256>>>(A, B, part, kS, Nn, kD);
    else
        gemm_splitk_kernel<128, 32, 16, 8, 4><<<grid, 128>>>(A, B, part, kS, Nn, kD);
    int MN = kS * Nn;
    splitk_reduce_kernel<<<(MN + 255) / 256, 256>>>(part, out, MN, act);
}

// big NT GEMM on tensor cores: C = A @ W^T (+resid), fp32 in/out, bf16x3 inside
static void big_gemm_tc(const float* A, const float* W, float* C, const float* resid,
                        __nv_bfloat16* ah, __nv_bfloat16* al,
                        __nv_bfloat16* wh, __nv_bfloat16* wl)
{
    int n4 = (int)(kSD / 4);
    split_bf16_kernel<<<n4 / 256, 256>>>((const float4*)A, (__nv_bfloat162*)ah,
                                         (__nv_bfloat162*)al, n4);
    split_bf16_kernel<<<n4 / 256, 256>>>((const float4*)W, (__nv_bfloat162*)wh,
                                         (__nv_bfloat162*)wl, n4);
    cudaFuncSetAttribute(bf16x3_nt_kernel, cudaFuncAttributeMaxDynamicSharedMemorySize, kSMEM);
    dim3 grid(16, 16);
    bf16x3_nt_kernel<<<grid, 256, kSMEM>>>(ah, al, wh, wl, C, resid, kD,
                                           0, nullptr, nullptr);
}

// medium NN GEMM on tensor cores: C = A[S,K] @ W[K,2048] with fused activation
static void med_gemm_tc(const float* A, const float* W, float* C, int K,
                        int act, const float* bias, const float* aux,
                        __nv_bfloat16* ah, __nv_bfloat16* al,
                        __nv_bfloat16* wh, __nv_bfloat16* wl)
{
    int n4 = kS * K / 4;
    split_bf16_kernel<<<(n4 + 255) / 256, 256>>>((const float4*)A, (__nv_bfloat162*)ah,
                                                 (__nv_bfloat162*)al, n4);
    tsplit_kernel<<<kD / 32, 256>>>(W, wh, wl, K, kD);
    cudaFuncSetAttribute(bf16x3_nt_kernel, cudaFuncAttributeMaxDynamicSharedMemorySize, kSMEM);
    dim3 grid(16, 16);
    bf16x3_nt_kernel<<<grid, 256, kSMEM>>>(ah, al, wh, wl, C, nullptr, K,
                                           act, bias, aux);
}

extern "C" void kernel_launch(void* const* d_in, const int* in_sizes, int n_in,
                              void* d_out, int out_size)
{
    (void)in_sizes; (void)n_in;
    const float* x      = (const float*)d_in[0];
    const float* st1    = (const float*)d_in[1];
    const float* st2    = (const float*)d_in[2];
    const float* vfirst = (const float*)d_in[3];
    const float* ln1w   = (const float*)d_in[4];
    const float* ln1b   = (const float*)d_in[5];
    const float* m_r    = (const float*)d_in[6];
    const float* m_w    = (const float*)d_in[7];
    const float* m_k    = (const float*)d_in[8];
    const float* m_v    = (const float*)d_in[9];
    const float* m_a    = (const float*)d_in[10];
    const float* m_g    = (const float*)d_in[11];
    const float* Wr     = (const float*)d_in[12];
    const float* Wk     = (const float*)d_in[13];
    const float* Wv     = (const float*)d_in[14];
    const float* Wo     = (const float*)d_in[15];
    const float* w1     = (const float*)d_in[16];
    const float* w2     = (const float*)d_in[17];
    const float* w0     = (const float*)d_in[18];
    const float* a1     = (const float*)d_in[19];
    const float* a2     = (const float*)d_in[20];
    const float* a0     = (const float*)d_in[21];
    const float* g1     = (const float*)d_in[22];
    const float* g2     = (const float*)d_in[23];
    const float* v1     = (const float*)d_in[24];
    const float* v2     = (const float*)d_in[25];
    const float* v0     = (const float*)d_in[26];
    const float* k_k    = (const float*)d_in[27];
    const float* k_a    = (const float*)d_in[28];
    const float* r_k    = (const float*)d_in[29];
    const float* lnxw   = (const float*)d_in[30];
    const float* lnxb   = (const float*)d_in[31];

    float* out = (float*)d_out;
    float* s1out = nullptr;
    float* s2out = nullptr;
    long long total1 = (long long)kSD + kD;
    long long total2 = total1 + (long long)kH * kN * kN;
    if ((long long)out_size >= total1) s1out = out + kSD;
    if ((long long)out_size >= total2) s2out = out + kSD + kD;

    float* p_xn   = getsym(g_xn);
    float* p_xr   = getsym(g_xr);
    float* p_xw   = getsym(g_xw);
    float* p_xk   = getsym(g_xk);
    float* p_xv   = getsym(g_xv);
    float* p_xa   = getsym(g_xa);
    float* p_xg   = getsym(g_xg);
    float* p_r    = getsym(g_r);
    float* p_k    = getsym(g_k);
    float* p_v    = getsym(g_v);
    float* p_a    = getsym(g_a);
    float* p_wdec = getsym(g_wdec);
    float* p_gate = getsym(g_gate);
    float* p_kk   = getsym(g_kk);
    float* p_b    = getsym(g_b);
    float* p_y    = getsym(g_y);
    float* p_opre = getsym(g_opre);
    float* p_t1   = getsym(g_t1);
    float* p_part = getsym(g_part);
    __nv_bfloat16* p_ah = getsym_bf(g_ah);
    __nv_bfloat16* p_al = getsym_bf(g_al);
    __nv_bfloat16* p_wh = getsym_bf(g_wh);
    __nv_bfloat16* p_wl = getsym_bf(g_wl);

    int ew_blocks = (int)(kSD / 256);

    // 1. LN + state1_out
    ln_kernel<<<kS, 256>>>(x, ln1w, ln1b, p_xn, s1out);
    // 2. token shift + mixes
    shift_mix_kernel<<<ew_blocks, 256>>>(p_xn, st1, m_r, m_w, m_k, m_v, m_a, m_g);
    // 3. big projections on tensor cores: r/k/v = x? @ W?^T
    big_gemm_tc(p_xr, Wr, p_r, nullptr, p_ah, p_al, p_wh, p_wl);
    big_gemm_tc(p_xk, Wk, p_k, nullptr, p_ah, p_al, p_wh, p_wl);
    big_gemm_tc(p_xv, Wv, p_v, nullptr, p_ah, p_al, p_wh, p_wl);
    // 4a. gate chain: sigmoid(xg@g1)@g2
    thin_gemm(p_xg, g1, p_t1, 128, /*sigmoid*/1, p_part);
    med_gemm_tc(p_t1, g2, p_gate, 128, 0, nullptr, nullptr, p_ah, p_al, p_wh, p_wl);
    // 4b. a chain: a = sigmoid(xa@a1@a2 + a0)
    thin_gemm(p_xa, a1, p_t1, 64, 0, p_part);
    med_gemm_tc(p_t1, a2, p_a, 64, 2, a0, nullptr, p_ah, p_al, p_wh, p_wl);
    // 4c. w chain: wdec = exp(-0.606531*sigmoid(tanh(xw@w1)@w2 + w0))
    thin_gemm(p_xw, w1, p_t1, 64, /*tanh*/2, p_part);
    med_gemm_tc(p_t1, w2, p_wdec, 64, 3, w0, nullptr, p_ah, p_al, p_wh, p_wl);
    // 4d. v chain: v += (vfirst - v)*sigmoid(xv@v1@v2 + v0)
    thin_gemm(p_xv, v1, p_t1, 32, 0, p_part);
    med_gemm_tc(p_t1, v2, p_v, 32, 4, v0, vfirst, p_ah, p_al, p_wh, p_wl);
    // 5. per-(s,h) prep
    prep_kernel<<<(kS * kH) / 8, 256>>>(p_k, p_a, k_k, k_a, p_kk, p_b, p_k);
    // 6. sequential scan (cp.async ring) + state2_out
    scan3_kernel<<<kH, 256>>>(p_r, p_wdec, p_k, p_v, p_kk, p_b, st2, p_y, s2out);
    // 7. groupnorm + rkv + gate
    post_kernel<<<(kS * kH) / 8, 256>>>(p_y, p_r, p_k, p_v, r_k, lnxw, lnxb, p_gate, p_opre);
    // 8. output projection on tensor cores with residual: out = x + opre @ Wo^T
    big_gemm_tc(p_opre, Wo, out, x, p_ah, p_al, p_wh, p_wl);
}

// round 11
// speedup vs baseline: 1.0467x; 1.0126x over previous
#include <cuda_runtime.h>
#include <cuda_bf16.h>
#include <math.h>
#include <stdint.h>

static constexpr int kS = 2048;
static constexpr int kD = 2048;
static constexpr int kH = 32;
static constexpr int kN = 64;
static constexpr size_t kSD = (size_t)kS * kD;
static constexpr int kKSPLIT = 16;
static constexpr int kC  = 32;            // chunk length
static constexpr int kNC = kS / kC;       // 64 chunks
static constexpr int kCDAT = 9280;        // floats per (h,c): E2048 F1024 G4096 H2048 Wc64

// ---------------- scratch ----------------
__device__ float g_xn[kSD];
__device__ float g_xr[kSD];
__device__ float g_xw[kSD];
__device__ float g_xk[kSD];
__device__ float g_xv[kSD];
__device__ float g_xa[kSD];
__device__ float g_xg[kSD];
__device__ float g_r[kSD];
__device__ float g_k[kSD];
__device__ float g_v[kSD];
__device__ float g_a[kSD];
__device__ float g_wdec[kSD];
__device__ float g_gate[kSD];
__device__ float g_kk[kSD];
__device__ float g_b[kSD];
__device__ float g_y[kSD];
__device__ float g_opre[kSD];
__device__ float g_t1[(size_t)kS * 128];
__device__ float g_part[(size_t)kKSPLIT * kS * 128];
__device__ float g_cdat[(size_t)kH * kNC * kCDAT];
__device__ __nv_bfloat16 g_ah[kSD];
__device__ __nv_bfloat16 g_al[kSD];
__device__ __nv_bfloat16 g_wh[kSD];
__device__ __nv_bfloat16 g_wl[kSD];

__device__ __forceinline__ float warp_sum(float v) {
    #pragma unroll
    for (int o = 16; o > 0; o >>= 1) v += __shfl_xor_sync(0xffffffffu, v, o);
    return v;
}
__device__ __forceinline__ float sigmoidf_(float x) { return 1.f / (1.f + expf(-x)); }

__device__ __forceinline__ float2 ffma2(float2 a, float2 b, float2 c) {
    float2 d;
    asm("fma.rn.f32x2 %0, %1, %2, %3;"
        : "=l"(reinterpret_cast<unsigned long long&>(d))
        : "l"(reinterpret_cast<unsigned long long&>(a)),
          "l"(reinterpret_cast<unsigned long long&>(b)),
          "l"(reinterpret_cast<unsigned long long&>(c)));
    return d;
}
__device__ __forceinline__ float2 fmul2(float2 a, float2 b) {
    float2 d;
    asm("mul.rn.f32x2 %0, %1, %2;"
        : "=l"(reinterpret_cast<unsigned long long&>(d))
        : "l"(reinterpret_cast<unsigned long long&>(a)),
          "l"(reinterpret_cast<unsigned long long&>(b)));
    return d;
}

__device__ __forceinline__ uint32_t smem_u32(const void* p) {
    return (uint32_t)__cvta_generic_to_shared(p);
}
__device__ __forceinline__ void cp16(uint32_t dst, const void* src) {
    asm volatile("cp.async.cg.shared.global [%0], [%1], 16;" :: "r"(dst), "l"(src));
}
__device__ __forceinline__ void cp_commit() {
    asm volatile("cp.async.commit_group;" ::: "memory");
}
template<int N>
__device__ __forceinline__ void cp_wait() {
    asm volatile("cp.async.wait_group %0;" :: "n"(N) : "memory");
}
__device__ __forceinline__ void ldsm_x4(uint32_t* r, uint32_t addr) {
    asm volatile("ldmatrix.sync.aligned.m8n8.x4.shared.b16 {%0,%1,%2,%3}, [%4];"
                 : "=r"(r[0]), "=r"(r[1]), "=r"(r[2]), "=r"(r[3]) : "r"(addr));
}
__device__ __forceinline__ void mma_bf16(float* c, const uint32_t* a, uint32_t b0, uint32_t b1) {
    asm volatile("mma.sync.aligned.m16n8k16.row.col.f32.bf16.bf16.f32 "
                 "{%0,%1,%2,%3}, {%4,%5,%6,%7}, {%8,%9}, {%0,%1,%2,%3};"
                 : "+f"(c[0]), "+f"(c[1]), "+f"(c[2]), "+f"(c[3])
                 : "r"(a[0]), "r"(a[1]), "r"(a[2]), "r"(a[3]), "r"(b0), "r"(b1));
}

// ---------------- fp32 -> (hi, lo) bf16 split ----------------
__global__ void split_bf16_kernel(const float4* __restrict__ src,
                                  __nv_bfloat162* __restrict__ hi,
                                  __nv_bfloat162* __restrict__ lo, int n4)
{
    int i = blockIdx.x * blockDim.x + threadIdx.x;
    if (i >= n4) return;
    float4 v = src[i];
    __nv_bfloat16 h0 = __float2bfloat16_rn(v.x);
    __nv_bfloat16 h1 = __float2bfloat16_rn(v.y);
    __nv_bfloat16 h2 = __float2bfloat16_rn(v.z);
    __nv_bfloat16 h3 = __float2bfloat16_rn(v.w);
    __nv_bfloat16 l0 = __float2bfloat16_rn(v.x - __bfloat162float(h0));
    __nv_bfloat16 l1 = __float2bfloat16_rn(v.y - __bfloat162float(h1));
    __nv_bfloat16 l2 = __float2bfloat16_rn(v.z - __bfloat162float(h2));
    __nv_bfloat16 l3 = __float2bfloat16_rn(v.w - __bfloat162float(h3));
    hi[2 * i + 0] = __nv_bfloat162(h0, h1);
    hi[2 * i + 1] = __nv_bfloat162(h2, h3);
    lo[2 * i + 0] = __nv_bfloat162(l0, l1);
    lo[2 * i + 1] = __nv_bfloat162(l2, l3);
}

// ---------------- transpose + split: W[K][N] f32 -> Th/Tl[N][K] bf16 ----------------
__global__ void tsplit_kernel(const float* __restrict__ W,
                              __nv_bfloat16* __restrict__ Th, __nv_bfloat16* __restrict__ Tl,
                              int K, int N)
{
    __shared__ float sm[128][33];
    int n0 = blockIdx.x * 32;
    int tid = threadIdx.x;
    int tn = tid & 31, tk = tid >> 5;
    for (int k = tk; k < K; k += 8)
        sm[k][tn] = W[(size_t)k * N + n0 + tn];
    __syncthreads();
    int rn = tid >> 3;
    int kper = K >> 3;
    int rk0 = (tid & 7) * kper;
    for (int q = 0; q < kper; q++) {
        int k = rk0 + q;
        float v = sm[k][rn];
        __nv_bfloat16 h = __float2bfloat16_rn(v);
        __nv_bfloat16 l = __float2bfloat16_rn(v - __bfloat162float(h));
        Th[(size_t)(n0 + rn) * K + k] = h;
        Tl[(size_t)(n0 + rn) * K + k] = l;
    }
}

// ---------------- bf16x3 tensor-core NT GEMM (runtime K) ----------------
static constexpr int kLDB  = 80;
static constexpr int kARR  = 128 * kLDB;
static constexpr int kSTG  = 4 * kARR;
static constexpr int kSMEM = 2 * kSTG;

__global__ void __launch_bounds__(256, 1)
bf16x3_nt_kernel(const __nv_bfloat16* __restrict__ Ah, const __nv_bfloat16* __restrict__ Al,
                 const __nv_bfloat16* __restrict__ Bh, const __nv_bfloat16* __restrict__ Bl,
                 float* __restrict__ C, const float* __restrict__ resid, int K,
                 int act, const float* __restrict__ bias, const float* __restrict__ aux)
{
    const int NT = K >> 5;
    extern __shared__ char sm_raw[];
    uint32_t sbase = smem_u32(sm_raw);

    int tid = threadIdx.x, lane = tid & 31, wid = tid >> 5;
    int m0 = blockIdx.y * 128, n0 = blockIdx.x * 128;
    int wm = (wid >> 2) * 64;
    int wn = (wid & 3) * 32;

    float acc[4][4][4];
    #pragma unroll
    for (int mt = 0; mt < 4; mt++)
        #pragma unroll
        for (int nt = 0; nt < 4; nt++)
            #pragma unroll
            for (int q = 0; q < 4; q++) acc[mt][nt][q] = 0.f;

    int seg = tid & 3;
    int r0 = tid >> 2;
    const char* sAh0 = (const char*)(Ah + (size_t)(m0 + r0) * K + seg * 8);
    const char* sAl0 = (const char*)(Al + (size_t)(m0 + r0) * K + seg * 8);
    const char* sBh0 = (const char*)(Bh + (size_t)(n0 + r0) * K + seg * 8);
    const char* sBl0 = (const char*)(Bl + (size_t)(n0 + r0) * K + seg * 8);
    const size_t rstep = (size_t)64 * K * 2;
    uint32_t d0 = (uint32_t)(r0 * kLDB + seg * 16);
    uint32_t d1 = (uint32_t)((r0 + 64) * kLDB + seg * 16);

    auto issue = [&](int kt) {
        uint32_t sb = sbase + (uint32_t)(kt & 1) * kSTG;
        size_t koff = (size_t)kt * 64;
        cp16(sb + 0 * kARR + d0, sAh0 + koff);
        cp16(sb + 0 * kARR + d1, sAh0 + rstep + koff);
        cp16(sb + 1 * kARR + d0, sAl0 + koff);
        cp16(sb + 1 * kARR + d1, sAl0 + rstep + koff);
        cp16(sb + 2 * kARR + d0, sBh0 + koff);
        cp16(sb + 2 * kARR + d1, sBh0 + rstep + koff);
        cp16(sb + 3 * kARR + d0, sBl0 + koff);
        cp16(sb + 3 * kARR + d1, sBl0 + rstep + koff);
        cp_commit();
    };

    issue(0);

    int frow = lane & 15;
    uint32_t fcol = (uint32_t)((lane >> 4) * 16);

    for (int kt = 0; kt < NT; ++kt) {
        if (kt + 1 < NT) { issue(kt + 1); cp_wait<1>(); }
        else             { cp_wait<0>(); }
        __syncthreads();

        uint32_t sb = sbase + (uint32_t)(kt & 1) * kSTG;
        #pragma unroll
        for (int kh = 0; kh < 2; kh++) {
            uint32_t kb = fcol + (uint32_t)(kh * 32);
            uint32_t ah[4][4], al[4][4], bh[2][4], bl[2][4];
            #pragma unroll
            for (int mt = 0; mt < 4; mt++) {
                uint32_t ro = (uint32_t)((wm + mt * 16 + frow) * kLDB) + kb;
                ldsm_x4(ah[mt], sb + 0 * kARR + ro);
                ldsm_x4(al[mt], sb + 1 * kARR + ro);
            }
            #pragma unroll
            for (int g = 0; g < 2; g++) {
                uint32_t ro = (uint32_t)((wn + g * 16 + frow) * kLDB) + kb;
                ldsm_x4(bh[g], sb + 2 * kARR + ro);
                ldsm_x4(bl[g], sb + 3 * kARR + ro);
            }
            #pragma unroll
            for (int mt = 0; mt < 4; mt++) {
                #pragma unroll
                for (int nt = 0; nt < 4; nt++) {
                    int g = nt >> 1, hf = nt & 1;
                    mma_bf16(acc[mt][nt], ah[mt], bh[g][hf], bh[g][2 + hf]);
                    mma_bf16(acc[mt][nt], ah[mt], bl[g][hf], bl[g][2 + hf]);
                    mma_bf16(acc[mt][nt], al[mt], bh[g][hf], bh[g][2 + hf]);
                }
            }
        }
        __syncthreads();
    }

    int crow = lane >> 2;
    int ccol = (lane & 3) * 2;
    #pragma unroll
    for (int mt = 0; mt < 4; mt++) {
        #pragma unroll
        for (int nt = 0; nt < 4; nt++) {
            int row = m0 + wm + mt * 16 + crow;
            int col = n0 + wn + nt * 8 + ccol;
            #pragma unroll
            for (int half = 0; half < 2; half++) {
                int rr = row + half * 8;
                size_t off = (size_t)rr * 2048 + col;
                float e0 = acc[mt][nt][half * 2 + 0];
                float e1 = acc[mt][nt][half * 2 + 1];
                if (act == 0) {
                    if (resid) {
                        const float2 rv = *(const float2*)(resid + off);
                        e0 += rv.x; e1 += rv.y;
                    }
                    *(float2*)(C + off) = make_float2(e0, e1);
                } else if (act == 2) {
                    e0 = sigmoidf_(e0 + bias[col]);
                    e1 = sigmoidf_(e1 + bias[col + 1]);
                    *(float2*)(C + off) = make_float2(e0, e1);
                } else if (act == 3) {
                    e0 = expf(-0.606531f * sigmoidf_(e0 + bias[col]));
                    e1 = expf(-0.606531f * sigmoidf_(e1 + bias[col + 1]));
                    *(float2*)(C + off) = make_float2(e0, e1);
                } else {
                    float sg0 = sigmoidf_(e0 + bias[col]);
                    float sg1 = sigmoidf_(e1 + bias[col + 1]);
                    float2 cv = *(const float2*)(C + off);
                    float2 av = *(const float2*)(aux + off);
                    cv.x += (av.x - cv.x) * sg0;
                    cv.y += (av.y - cv.y) * sg1;
                    *(float2*)(C + off) = cv;
                }
            }
        }
    }
}

// ---------------- LayerNorm ----------------
__global__ void ln_kernel(const float* __restrict__ x, const float* __restrict__ w,
                          const float* __restrict__ b, float* __restrict__ xn,
                          float* __restrict__ s1out)
{
    int s = blockIdx.x;
    int tid = threadIdx.x;
    size_t base = (size_t)s * kD;
    float vals[8];
    float sum = 0.f, sq = 0.f;
    #pragma unroll
    for (int i = 0; i < 8; i++) {
        float v = x[base + tid + i * 256];
        vals[i] = v; sum += v; sq += v * v;
    }
    __shared__ float sh1[256], sh2[256];
    sh1[tid] = sum; sh2[tid] = sq;
    __syncthreads();
    for (int off = 128; off > 0; off >>= 1) {
        if (tid < off) { sh1[tid] += sh1[tid + off]; sh2[tid] += sh2[tid + off]; }
        __syncthreads();
    }
    float mean = sh1[0] * (1.f / kD);
    float var  = sh2[0] * (1.f / kD) - mean * mean;
    float rstd = rsqrtf(var + 1e-5f);
    #pragma unroll
    for (int i = 0; i < 8; i++) {
        int d = tid + i * 256;
        float o = (vals[i] - mean) * rstd * w[d] + b[d];
        xn[base + d] = o;
        if (s1out && s == kS - 1) s1out[d] = o;
    }
}

// ---------------- token shift + 6 mixes ----------------
__global__ void shift_mix_kernel(const float* __restrict__ xn, const float* __restrict__ st1,
    const float* __restrict__ mr, const float* __restrict__ mw, const float* __restrict__ mk,
    const float* __restrict__ mv, const float* __restrict__ ma, const float* __restrict__ mg)
{
    size_t idx = (size_t)blockIdx.x * blockDim.x + threadIdx.x;
    if (idx >= kSD) return;
    int d = (int)(idx & (size_t)(kD - 1));
    float cur = xn[idx];
    float past = (idx < (size_t)kD) ? st1[d] : xn[idx - kD];
    float sx = past - cur;
    g_xr[idx] = cur + sx * mr[d];
    g_xw[idx] = cur + sx * mw[d];
    g_xk[idx] = cur + sx * mk[d];
    g_xv[idx] = cur + sx * mv[d];
    g_xa[idx] = cur + sx * ma[d];
    g_xg[idx] = cur + sx * mg[d];
}

// ---------------- split-K thin GEMM ----------------
template<int BM, int BN, int BK, int TM, int TN>
__global__ void __launch_bounds__((BM/TM)*(BN/TN))
gemm_splitk_kernel(const float* __restrict__ A, const float* __restrict__ B,
                   float* __restrict__ part, int M, int Nn, int K)
{
    constexpr int THREADS = (BM / TM) * (BN / TN);
    __shared__ float As[BK][BM + 4];
    __shared__ float Bs[BK][BN + 4];
    int tid = threadIdx.x;
    int m0 = blockIdx.y * BM;
    int ks = blockIdx.z;
    int kc = K / kKSPLIT;
    int kbeg = ks * kc;
    int tx = tid % (BN / TN);
    int ty = tid / (BN / TN);
    float acc[TM][TN];
    #pragma unroll
    for (int i = 0; i < TM; i++)
        #pragma unroll
        for (int j = 0; j < TN; j++) acc[i][j] = 0.f;

    constexpr int KQ = BK / 4;
    constexpr int A_F4 = BM * BK / 4;
    constexpr int A_PER = A_F4 / THREADS;
    static_assert(A_F4 % THREADS == 0, "A load");
    constexpr int B_F4 = BN * BK / 4;
    constexpr int B_PER = B_F4 / THREADS;
    static_assert(B_F4 % THREADS == 0, "B load");
    constexpr int NQ = BN / 4;

    for (int k0 = kbeg; k0 < kbeg + kc; k0 += BK) {
        #pragma unroll
        for (int i = 0; i < A_PER; i++) {
            int e = tid + i * THREADS;
            int row = e / KQ, kq = e % KQ;
            float4 v = *(const float4*)&A[(size_t)(m0 + row) * K + k0 + kq * 4];
            As[kq * 4 + 0][row] = v.x; As[kq * 4 + 1][row] = v.y;
            As[kq * 4 + 2][row] = v.z; As[kq * 4 + 3][row] = v.w;
        }
        #pragma unroll
        for (int i = 0; i < B_PER; i++) {
            int e = tid + i * THREADS;
            int row = e / NQ, nq = e % NQ;
            float4 v = *(const float4*)&B[(size_t)(k0 + row) * Nn + nq * 4];
            *(float4*)&Bs[row][nq * 4] = v;
        }
        __syncthreads();
        #pragma unroll
        for (int k = 0; k < BK; k++) {
            float af[TM], bf[TN];
            #pragma unroll
            for (int i = 0; i < TM; i++) af[i] = As[k][ty * TM + i];
            #pragma unroll
            for (int j = 0; j < TN; j++) bf[j] = Bs[k][tx * TN + j];
            #pragma unroll
            for (int i = 0; i < TM; i++)
                #pragma unroll
                for (int j = 0; j < TN; j++)
                    acc[i][j] += af[i] * bf[j];
        }
        __syncthreads();
    }
    float* pbase = part + (size_t)ks * M * Nn;
    #pragma unroll
    for (int i = 0; i < TM; i++) {
        size_t rowoff = (size_t)(m0 + ty * TM + i) * Nn + tx * TN;
        #pragma unroll
        for (int j = 0; j < TN; j++) pbase[rowoff + j] = acc[i][j];
    }
}

__global__ void splitk_reduce_kernel(const float* __restrict__ part, float* __restrict__ out,
                                     int MN, int act)
{
    int i = blockIdx.x * blockDim.x + threadIdx.x;
    if (i >= MN) return;
    float s = 0.f;
    #pragma unroll
    for (int ks = 0; ks < kKSPLIT; ks++) s += part[(size_t)ks * MN + i];
    if (act == 1) s = sigmoidf_(s);
    else if (act == 2) s = tanhf(s);
    out[i] = s;
}

// ---------------- per-(s,h) prep ----------------
__global__ void prep_kernel(const float* __restrict__ k_in, const float* __restrict__ a,
                            const float* __restrict__ k_k, const float* __restrict__ k_a,
                            float* __restrict__ kk_out, float* __restrict__ b_out,
                            float* __restrict__ k_out)
{
    int gwarp = (int)((blockIdx.x * (size_t)blockDim.x + threadIdx.x) >> 5);
    int lane = threadIdx.x & 31;
    if (gwarp >= kS * kH) return;
    int s = gwarp >> 5, h = gwarp & (kH - 1);
    size_t base = (size_t)s * kD + (size_t)h * kN;
    int d0 = h * kN + lane, d1 = d0 + 32;
    float k0 = k_in[base + lane], k1 = k_in[base + lane + 32];
    float kk0 = k0 * k_k[d0], kk1 = k1 * k_k[d1];
    float ss = warp_sum(kk0 * kk0 + kk1 * kk1);
    float inv = 1.f / fmaxf(sqrtf(ss), 1e-12f);
    kk0 *= inv; kk1 *= inv;
    float a0 = a[base + lane], a1 = a[base + lane + 32];
    kk_out[base + lane] = kk0;        kk_out[base + lane + 32] = kk1;
    b_out[base + lane]  = kk0 * a0;   b_out[base + lane + 32]  = kk1 * a1;
    k_out[base + lane]      = k0 * (1.f + (a0 - 1.f) * k_a[d0]);
    k_out[base + lane + 32] = k1 * (1.f + (a1 - 1.f) * k_a[d1]);
}

// ================== chunked scan phase A: per-(chunk, head) matrices ==================
// S_t = S_{t-1}(diag(w_t)+a_t b_t^T)+v_t k_t^T, a=-kk. Outputs E,F,G,H,Wc per chunk:
// Y = E S0^T + F V ;  S_C = S0 (diag(Wc)+G) + V^T H
static constexpr int kP65 = 65;   // padded smem row stride (bank-conflict-free column reads)
static constexpr int kASMEM = (2112 + 4 * 2080 + 7 * 1024 + 2080) * 4;   // 78720 B

__global__ void __launch_bounds__(128, 2)
chunkA_kernel(const float* __restrict__ w, const float* __restrict__ kkv,
              const float* __restrict__ bv, const float* __restrict__ kv,
              const float* __restrict__ rv, float* __restrict__ cdat)
{
    int c = blockIdx.x, h = blockIdx.y;
    int tid = threadIdx.x;
    extern __shared__ float sm[];
    float* Wcum = sm;              // 33*64
    float* alp  = Wcum + 2112;     // 32*65
    float* bet  = alp + 2080;
    float* kap  = bet + 2080;
    float* rho  = kap + 2080;
    float* P    = rho + 2080;      // 32*32 each
    float* Q    = P + 1024;
    float* M1   = Q + 1024;
    float* M2   = M1 + 1024;
    float* T    = M2 + 1024;
    float* TQ   = T + 1024;
    float* M1T  = TQ + 1024;
    float* wtmp = M1T + 1024;      // 32*65: w, later T^T B

    size_t gbase = (size_t)(c * kC) * kD + (size_t)h * kN;
    for (int e = tid; e < kC * kN; e += 128) {
        int t = e >> 6, j = e & 63;
        size_t go = gbase + (size_t)t * kD + j;
        int o = t * kP65 + j;
        wtmp[o] = w[go];
        alp[o]  = kkv[go];
        bet[o]  = bv[go];
        kap[o]  = kv[go];
        rho[o]  = rv[go];
    }
    __syncthreads();
    if (tid < 64) {
        float acc = 1.f;
        Wcum[tid] = 1.f;
        for (int t = 0; t < kC; t++) {
            acc *= wtmp[t * kP65 + tid];
            Wcum[(t + 1) * 64 + tid] = acc;
        }
    }
    __syncthreads();
    for (int e = tid; e < kC * kN; e += 128) {
        int t = e >> 6, j = e & 63;
        int o = t * kP65 + j;
        float wprev = Wcum[t * 64 + j], wcur = Wcum[(t + 1) * 64 + j];
        float iw = 1.f / wcur;
        alp[o] = -wprev * alp[o];     // alpha_t = W_{t-1} * (-kk_t)
        bet[o] = bet[o] * iw;         // beta_s  = b_s / W_s
        kap[o] = kap[o] * iw;         // kappa_s = k_s / W_s
        rho[o] = wcur * rho[o];       // rho_t   = W_t * r_t
    }
    __syncthreads();
    // P,Q strict (alp x bet / alp x kap); M1,M2 inclusive (rho x bet / rho x kap)
    for (int e = tid; e < 4096; e += 128) {
        int mat = e >> 10, idx = e & 1023, t = idx >> 5, s = idx & 31;
        bool on = (mat < 2) ? (s < t) : (s <= t);
        float out = 0.f;
        if (on) {
            const float* L = (mat < 2) ? (alp + t * kP65) : (rho + t * kP65);
            const float* R = ((mat & 1) == 0) ? (bet + s * kP65) : (kap + s * kP65);
            float acc = 0.f;
            for (int j = 0; j < 64; j++) acc += L[j] * R[j];
            out = acc;
        }
        float* dst = (mat == 0) ? P : (mat == 1) ? Q : (mat == 2) ? M1 : M2;
        dst[idx] = out;
    }
    __syncthreads();
    // T = (I - P)^{-1} forward substitution; column col owned by one thread
    if (tid < 32) {
        int col = tid;
        for (int t = 0; t < kC; t++) {
            float val = (t == col) ? 1.f : 0.f;
            for (int s = 0; s < t; s++) val += P[t * 32 + s] * T[s * 32 + col];
            T[t * 32 + col] = val;
        }
    }
    __syncthreads();
    // TQ = T@Q ; M1T = M1@T
    for (int e = tid; e < 2048; e += 128) {
        int which = e >> 10, idx = e & 1023, t = idx >> 5, s = idx & 31;
        float acc = 0.f;
        if (which == 0) { for (int m = 0; m < 32; m++) acc += T[t * 32 + m] * Q[m * 32 + s]; }
        else            { for (int m = 0; m < 32; m++) acc += M1[t * 32 + m] * T[m * 32 + s]; }
        (which ? M1T : TQ)[idx] = acc;
    }
    __syncthreads();
    float* outp = cdat + (size_t)(h * kNC + c) * kCDAT;
    // E = rho + M1T @ alpha  (32x64)
    for (int e = tid; e < 2048; e += 128) {
        int t = e >> 6, j = e & 63;
        float acc = rho[t * kP65 + j];
        for (int s = 0; s < 32; s++) acc += M1T[t * 32 + s] * alp[s * kP65 + j];
        outp[e] = acc;
    }
    // F = M1 @ TQ + M2  (32x32)
    for (int e = tid; e < 1024; e += 128) {
        int t = e >> 5, s = e & 31;
        float acc = M2[e];
        for (int m = 0; m < 32; m++) acc += M1[t * 32 + m] * TQ[m * 32 + s];
        outp[2048 + e] = acc;
    }
    __syncthreads();
    // wtmp := T^T @ beta
    for (int e = tid; e < 2048; e += 128) {
        int x = e >> 6, j = e & 63;
        float acc = 0.f;
        for (int s = 0; s < 32; s++) acc += T[s * 32 + x] * bet[s * kP65 + j];
        wtmp[x * kP65 + j] = acc;
    }
    __syncthreads();
    // G[m][j] = Wc[j] * sum_x alpha[x][m] * (T^T B)[x][j]   (64x64)
    for (int e = tid; e < 4096; e += 128) {
        int m = e >> 6, j = e & 63;
        float wc = Wcum[2048 + j];
        float acc = 0.f;
        for (int x = 0; x < 32; x++) acc += alp[x * kP65 + m] * wtmp[x * kP65 + j];
        outp[3072 + e] = wc * acc;
    }
    // H[s][j] = Wc[j] * ((TQ)^T B + kappa)[s][j]   (32x64)
    for (int e = tid; e < 2048; e += 128) {
        int s = e >> 6, j = e & 63;
        float wc = Wcum[2048 + j];
        float acc = kap[s * kP65 + j];
        for (int x = 0; x < 32; x++) acc += TQ[x * 32 + s] * bet[x * kP65 + j];
        outp[7168 + e] = wc * acc;
    }
    if (tid < 64) outp[9216 + tid] = Wcum[2048 + tid];
}

// ================== chunked scan phase B: sequential over 64 chunks ==================
static constexpr int kBBUF  = kCDAT + kC * kN;                 // 11328 floats
static constexpr int kBSMEM = (2 * kBBUF + 64 * 66) * 4;       // 107520 B

__global__ void __launch_bounds__(256, 1)
chunkB_kernel(const float* __restrict__ cdat, const float* __restrict__ v,
              const float* __restrict__ st2_in, float* __restrict__ y,
              float* __restrict__ st2_out)
{
    int h = blockIdx.x;
    int tid = threadIdx.x, jq = tid & 3, i = tid >> 2;
    extern __shared__ float sm[];
    float* Scur = sm + 2 * kBBUF;

    float2 st[8];
    const float2* sin = (const float2*)(st2_in + (size_t)h * kN * kN + (size_t)i * kN + jq * 16);
    #pragma unroll
    for (int m = 0; m < 8; m++) st[m] = sin[m];

    auto issue = [&](int c, int bsel) {
        uint32_t dst = smem_u32(sm + bsel * kBBUF);
        const float* src = cdat + (size_t)(h * kNC + c) * kCDAT;
        for (int e = tid; e < kCDAT / 4; e += 256) cp16(dst + (uint32_t)e * 16, src + e * 4);
        const float* vsrc = v + (size_t)(c * kC) * kD + (size_t)h * kN;
        uint32_t dv = dst + (uint32_t)kCDAT * 4;
        for (int e = tid; e < 512; e += 256) {
            int s = e >> 4, q = e & 15;
            cp16(dv + (uint32_t)(s * 256 + q * 16), vsrc + (size_t)s * kD + q * 4);
        }
        cp_commit();
    };

    issue(0, 0);

    for (int c = 0; c < kNC; c++) {
        int bsel = c & 1;
        if (c + 1 < kNC) { issue(c + 1, bsel ^ 1); cp_wait<1>(); }
        else             { cp_wait<0>(); }
        // dump chunk-start state into Scur
        float2* srow = (float2*)(Scur + i * 66 + jq * 16);
        #pragma unroll
        for (int m = 0; m < 8; m++) srow[m] = st[m];
        __syncthreads();

        const float* B  = sm + bsel * kBBUF;
        const float* sE = B;
        const float* sF = B + 2048;
        const float* sG = B + 3072;
        const float* sH = B + 7168;
        const float* sWc = B + 9216;
        const float* sV = B + 9280;

        // ---- Y = E S0^T + F V ----
        float accY[32];
        #pragma unroll
        for (int t = 0; t < 32; t++) {
            const float2* Er = (const float2*)(sE + t * 64 + jq * 16);
            float2 p = make_float2(0.f, 0.f);
            #pragma unroll
            for (int m = 0; m < 8; m++) p = ffma2(st[m], Er[m], p);
            accY[t] = p.x + p.y;
        }
        float vs[8];
        #pragma unroll
        for (int s8 = 0; s8 < 8; s8++) vs[s8] = sV[(jq * 8 + s8) * 64 + i];
        #pragma unroll
        for (int t = 0; t < 32; t++) {
            float q = 0.f;
            #pragma unroll
            for (int s8 = 0; s8 < 8; s8++) q += sF[t * 32 + jq * 8 + s8] * vs[s8];
            accY[t] += q;
        }
        size_t ybase = (size_t)(c * kC) * kD + (size_t)h * kN + i;
        #pragma unroll
        for (int t = 0; t < 32; t++) {
            float yv = accY[t];
            yv += __shfl_xor_sync(0xffffffffu, yv, 1);
            yv += __shfl_xor_sync(0xffffffffu, yv, 2);
            if (jq == 0) y[ybase + (size_t)t * kD] = yv;
        }

        // ---- S = S0 diag(Wc) + S0 G + V^T H ----
        float2 acc[8];
        const float2* wc2 = (const float2*)(sWc + jq * 16);
        #pragma unroll
        for (int m = 0; m < 8; m++) acc[m] = fmul2(st[m], wc2[m]);
        for (int m = 0; m < 64; m++) {
            float sim = Scur[i * 66 + m];
            float2 s2 = make_float2(sim, sim);
            const float2* Gr = (const float2*)(sG + m * 64 + jq * 16);
            #pragma unroll
            for (int q = 0; q < 8; q++) acc[q] = ffma2(s2, Gr[q], acc[q]);
        }
        for (int s = 0; s < 32; s++) {
            float vsi = sV[s * 64 + i];
            float2 v2 = make_float2(vsi, vsi);
            const float2* Hr = (const float2*)(sH + s * 64 + jq * 16);
            #pragma unroll
            for (int q = 0; q < 8; q++) acc[q] = ffma2(v2, Hr[q], acc[q]);
        }
        #pragma unroll
        for (int m = 0; m < 8; m++) st[m] = acc[m];
        __syncthreads();
    }
    if (st2_out) {
        float2* sout = (float2*)(st2_out + (size_t)h * kN * kN + (size_t)i * kN + jq * 16);
        #pragma unroll
        for (int m = 0; m < 8; m++) sout[m] = st[m];
    }
}

// ---------------- groupnorm + rkv + gate epilogue ----------------
__global__ void post_kernel(const float* __restrict__ y, const float* __restrict__ r,
                            const float* __restrict__ k, const float* __restrict__ v,
                            const float* __restrict__ r_k, const float* __restrict__ lnxw,
                            const float* __restrict__ lnxb, const float* __restrict__ gate,
                            float* __restrict__ opre)
{
    int gwarp = (int)((blockIdx.x * (size_t)blockDim.x + threadIdx.x) >> 5);
    int lane = threadIdx.x & 31;
    if (gwarp >= kS * kH) return;
    int s = gwarp >> 5, h = gwarp & (kH - 1);
    size_t base = (size_t)s * kD + (size_t)h * kN;
    int d0 = h * kN + lane, d1 = d0 + 32;
    float y0 = y[base + lane], y1 = y[base + lane + 32];
    float sum = warp_sum(y0 + y1);
    float sq  = warp_sum(y0 * y0 + y1 * y1);
    float mean = sum * (1.f / kN);
    float var  = sq * (1.f / kN) - mean * mean;
    float rstd = rsqrtf(var + 0.00064f);
    float o0 = (y0 - mean) * rstd * lnxw[d0] + lnxb[d0];
    float o1 = (y1 - mean) * rstd * lnxw[d1] + lnxb[d1];
    float r0 = r[base + lane], r1 = r[base + lane + 32];
    float k0 = k[base + lane], k1 = k[base + lane + 32];
    float dot = warp_sum(r0 * k0 * r_k[d0] + r1 * k1 * r_k[d1]);
    float v0 = v[base + lane], v1 = v[base + lane + 32];
    opre[base + lane]      = (o0 + dot * v0) * gate[base + lane];
    opre[base + lane + 32] = (o1 + dot * v1) * gate[base + lane + 32];
}

// ---------------- host side ----------------
static float* getsym(const void* symbol) {
    void* p = nullptr;
    cudaGetSymbolAddress(&p, symbol);
    return (float*)p;
}
static __nv_bfloat16* getsym_bf(const void* symbol) {
    void* p = nullptr;
    cudaGetSymbolAddress(&p, symbol);
    return (__nv_bfloat16*)p;
}

static void thin_gemm(const float* A, const float* B, float* out, int Nn, int act,
                      float* part) {
    dim3 grid(1, kS / 128, kKSPLIT);
    if (Nn == 128)
        gemm_splitk_kernel<128, 128, 16, 8, 8><<<grid, 256>>>(A, B, part, kS, Nn, kD);
    else if (Nn == 64)
        gemm_splitk_kernel<128, 64, 16, 8, 4><<<grid, 256>>>(A, B, part, kS, Nn, kD);
    else
        gemm_splitk_kernel<128, 32, 16, 8, 4><<<grid, 128>>>(A, B, part, kS, Nn, kD);
    int MN = kS * Nn;
    splitk_reduce_kernel<<<(MN + 255) / 256, 256>>>(part, out, MN, act);
}

static void big_gemm_tc(const float* A, const float* W, float* C, const float* resid,
                        __nv_bfloat16* ah, __nv_bfloat16* al,
                        __nv_bfloat16* wh, __nv_bfloat16* wl)
{
    int n4 = (int)(kSD / 4);
    split_bf16_kernel<<<n4 / 256, 256>>>((const float4*)A, (__nv_bfloat162*)ah,
                                         (__nv_bfloat162*)al, n4);
    split_bf16_kernel<<<n4 / 256, 256>>>((const float4*)W, (__nv_bfloat162*)wh,
                                         (__nv_bfloat162*)wl, n4);
    cudaFuncSetAttribute(bf16x3_nt_kernel, cudaFuncAttributeMaxDynamicSharedMemorySize, kSMEM);
    dim3 grid(16, 16);
    bf16x3_nt_kernel<<<grid, 256, kSMEM>>>(ah, al, wh, wl, C, resid, kD,
                                           0, nullptr, nullptr);
}

static void med_gemm_tc(const float* A, const float* W, float* C, int K,
                        int act, const float* bias, const float* aux,
                        __nv_bfloat16* ah, __nv_bfloat16* al,
                        __nv_bfloat16* wh, __nv_bfloat16* wl)
{
    int n4 = kS * K / 4;
    split_bf16_kernel<<<(n4 + 255) / 256, 256>>>((const float4*)A, (__nv_bfloat162*)ah,
                                                 (__nv_bfloat162*)al, n4);
    tsplit_kernel<<<kD / 32, 256>>>(W, wh, wl, K, kD);
    cudaFuncSetAttribute(bf16x3_nt_kernel, cudaFuncAttributeMaxDynamicSharedMemorySize, kSMEM);
    dim3 grid(16, 16);
    bf16x3_nt_kernel<<<grid, 256, kSMEM>>>(ah, al, wh, wl, C, nullptr, K,
                                           act, bias, aux);
}

extern "C" void kernel_launch(void* const* d_in, const int* in_sizes, int n_in,
                              void* d_out, int out_size)
{
    (void)in_sizes; (void)n_in;
    const float* x      = (const float*)d_in[0];
    const float* st1    = (const float*)d_in[1];
    const float* st2    = (const float*)d_in[2];
    const float* vfirst = (const float*)d_in[3];
    const float* ln1w   = (const float*)d_in[4];
    const float* ln1b   = (const float*)d_in[5];
    const float* m_r    = (const float*)d_in[6];
    const float* m_w    = (const float*)d_in[7];
    const float* m_k    = (const float*)d_in[8];
    const float* m_v    = (const float*)d_in[9];
    const float* m_a    = (const float*)d_in[10];
    const float* m_g    = (const float*)d_in[11];
    const float* Wr     = (const float*)d_in[12];
    const float* Wk     = (const float*)d_in[13];
    const float* Wv     = (const float*)d_in[14];
    const float* Wo     = (const float*)d_in[15];
    const float* w1     = (const float*)d_in[16];
    const float* w2     = (const float*)d_in[17];
    const float* w0     = (const float*)d_in[18];
    const float* a1     = (const float*)d_in[19];
    const float* a2     = (const float*)d_in[20];
    const float* a0     = (const float*)d_in[21];
    const float* g1     = (const float*)d_in[22];
    const float* g2     = (const float*)d_in[23];
    const float* v1     = (const float*)d_in[24];
    const float* v2     = (const float*)d_in[25];
    const float* v0     = (const float*)d_in[26];
    const float* k_k    = (const float*)d_in[27];
    const float* k_a    = (const float*)d_in[28];
    const float* r_k    = (const float*)d_in[29];
    const float* lnxw   = (const float*)d_in[30];
    const float* lnxb   = (const float*)d_in[31];

    float* out = (float*)d_out;
    float* s1out = nullptr;
    float* s2out = nullptr;
    long long total1 = (long long)kSD + kD;
    long long total2 = total1 + (long long)kH * kN * kN;
    if ((long long)out_size >= total1) s1out = out + kSD;
    if ((long long)out_size >= total2) s2out = out + kSD + kD;

    float* p_xn   = getsym(g_xn);
    float* p_xr   = getsym(g_xr);
    float* p_xw   = getsym(g_xw);
    float* p_xk   = getsym(g_xk);
    float* p_xv   = getsym(g_xv);
    float* p_xa   = getsym(g_xa);
    float* p_xg   = getsym(g_xg);
    float* p_r    = getsym(g_r);
    float* p_k    = getsym(g_k);
    float* p_v    = getsym(g_v);
    float* p_a    = getsym(g_a);
    float* p_wdec = getsym(g_wdec);
    float* p_gate = getsym(g_gate);
    float* p_kk   = getsym(g_kk);
    float* p_b    = getsym(g_b);
    float* p_y    = getsym(g_y);
    float* p_opre = getsym(g_opre);
    float* p_t1   = getsym(g_t1);
    float* p_part = getsym(g_part);
    float* p_cdat = getsym(g_cdat);
    __nv_bfloat16* p_ah = getsym_bf(g_ah);
    __nv_bfloat16* p_al = getsym_bf(g_al);
    __nv_bfloat16* p_wh = getsym_bf(g_wh);
    __nv_bfloat16* p_wl = getsym_bf(g_wl);

    int ew_blocks = (int)(kSD / 256);

    // 1. LN + state1_out
    ln_kernel<<<kS, 256>>>(x, ln1w, ln1b, p_xn, s1out);
    // 2. token shift + mixes
    shift_mix_kernel<<<ew_blocks, 256>>>(p_xn, st1, m_r, m_w, m_k, m_v, m_a, m_g);
    // 3. big projections (tensor cores)
    big_gemm_tc(p_xr, Wr, p_r, nullptr, p_ah, p_al, p_wh, p_wl);
    big_gemm_tc(p_xk, Wk, p_k, nullptr, p_ah, p_al, p_wh, p_wl);
    big_gemm_tc(p_xv, Wv, p_v, nullptr, p_ah, p_al, p_wh, p_wl);
    // 4a. gate chain
    thin_gemm(p_xg, g1, p_t1, 128, 1, p_part);
    med_gemm_tc(p_t1, g2, p_gate, 128, 0, nullptr, nullptr, p_ah, p_al, p_wh, p_wl);
    // 4b. a chain
    thin_gemm(p_xa, a1, p_t1, 64, 0, p_part);
    med_gemm_tc(p_t1, a2, p_a, 64, 2, a0, nullptr, p_ah, p_al, p_wh, p_wl);
    // 4c. w chain
    thin_gemm(p_xw, w1, p_t1, 64, 2, p_part);
    med_gemm_tc(p_t1, w2, p_wdec, 64, 3, w0, nullptr, p_ah, p_al, p_wh, p_wl);
    // 4d. v chain (RMW)
    thin_gemm(p_xv, v1, p_t1, 32, 0, p_part);
    med_gemm_tc(p_t1, v2, p_v, 32, 4, v0, vfirst, p_ah, p_al, p_wh, p_wl);
    // 5. prep
    prep_kernel<<<(kS * kH) / 8, 256>>>(p_k, p_a, k_k, k_a, p_kk, p_b, p_k);
    // 6. chunked scan: phase A (parallel) + phase B (64-chunk sequential)
    cudaFuncSetAttribute(chunkA_kernel, cudaFuncAttributeMaxDynamicSharedMemorySize, kASMEM);
    dim3 gA(kNC, kH);
    chunkA_kernel<<<gA, 128, kASMEM>>>(p_wdec, p_kk, p_b, p_k, p_r, p_cdat);
    cudaFuncSetAttribute(chunkB_kernel, cudaFuncAttributeMaxDynamicSharedMemorySize, kBSMEM);
    chunkB_kernel<<<kH, 256, kBSMEM>>>(p_cdat, p_v, st2, p_y, s2out);
    // 7. groupnorm + rkv + gate
    post_kernel<<<(kS * kH) / 8, 256>>>(p_y, p_r, p_k, p_v, r_k, lnxw, lnxb, p_gate, p_opre);
    // 8. output projection with residual
    big_gemm_tc(p_opre, Wo, out, x, p_ah, p_al, p_wh, p_wl);
}